// round 6
// baseline (speedup 1.0000x reference)
#include <cuda_runtime.h>
#include <cfloat>
#include <math.h>

// CrossFrameAttention: B=4, SAI=9, CK=CV=64, H=W=32
// out[b,c,hw] = softmax_k( Q[b,:,hw]·K[b,:,k] + bias[b,k] ) · V[b,k,:]
// keep(k) = |dist(b,s)*disp(b,hw_k)| > 0.5 ; p = keep ? exp(s) : 0 (static-max safe)
//
// QT=16, KC=64, 256 threads, 2 CTAs/SM (8 warps/SMSP) for latency hiding.
// Warps 0-3 (A): QK+exp loop. Warps 4-7 (B): AV loop. Parity named barriers.

#define SAI 9
#define NB 4
#define CKD 64
#define HWN 1024
#define CVD 64
#define QT 16
#define KC 64
#define NCHUNK 144          // 9 frames * (1024/64)
#define VSTR 68
#define PSTR 68

#define BID_READY0 1
#define BID_READY1 2
#define BID_FREE0  3
#define BID_FREE1  4
#define BID_GRPA   5
#define BID_GRPB   6

struct __align__(16) Smem {
    float Qsm[CKD][QT];           //  4 KB
    float Ks[2][CKD][KC];         // 32 KB  (K 2-stage, A-owned)
    float Vs[3][CVD][VSTR];       // 51 KB  (V 3-stage, B-owned)
    union {
        float  Ps[2][QT][PSTR];   // 8.5 KB (P 2-stage)
        float2 Obuf[64][16];      // 8 KB   epilogue only (after P reads done)
    };
    float Dsm[HWN];               //  4 KB
    float Lpart[4][4][4];
    float Dist[16];
    float Lb[QT];
};

__device__ __forceinline__ float2 ffma2(float2 a, float2 b, float2 c) {
    float2 d;
    asm("fma.rn.f32x2 %0, %1, %2, %3;"
        : "=l"(reinterpret_cast<unsigned long long &>(d))
        : "l"(reinterpret_cast<unsigned long long &>(a)),
          "l"(reinterpret_cast<unsigned long long &>(b)),
          "l"(reinterpret_cast<unsigned long long &>(c)));
    return d;
}

__device__ __forceinline__ void cpa16(const void* dst, const void* src) {
    unsigned d = (unsigned)__cvta_generic_to_shared(dst);
    asm volatile("cp.async.cg.shared.global [%0], [%1], 16;" :: "r"(d), "l"(src));
}

__device__ __forceinline__ void nbar_sync(int id, int cnt) {
    asm volatile("bar.sync %0, %1;" :: "r"(id), "r"(cnt) : "memory");
}
__device__ __forceinline__ void nbar_arrive(int id, int cnt) {
    asm volatile("bar.arrive %0, %1;" :: "r"(id), "r"(cnt) : "memory");
}

__global__ __launch_bounds__(256, 2)
void cfa_kernel(const float* __restrict__ gK, const float* __restrict__ gV,
                const float* __restrict__ gQ, const float* __restrict__ gD,
                const int*   __restrict__ gS, float* __restrict__ gO)
{
    extern __shared__ char raw[];
    Smem* sm = reinterpret_cast<Smem*>(raw);

    const int b   = blockIdx.y;
    const int hw0 = blockIdx.x * QT;
    const int tid = threadIdx.x;
    const bool isA = tid < 128;

    // A mapping (warps 0-3): warp w owns keys [16w,16w+16); lane = qg(4) + 4*kg(8)
    const int lane = tid & 31;
    const int w    = tid >> 5;
    const int qg   = lane & 3;
    const int kg   = lane >> 2;          // 0..7
    const int q0   = qg * 4;             // 4 queries
    const int k0   = w * 16 + kg * 2;    // 2 keys (float2)

    // B mapping (warps 4-7): ut in [0,128): kh(2) x qg2(4) x cg(16)
    const int ut  = tid & 127;
    const int kh  = ut >> 6;
    const int ul  = ut & 63;
    const int cg  = ul & 15;
    const int q0a = (ul >> 4) * 4;

    if (tid < SAI) {
        float x = (float)gS[(b * SAI + tid) * 2 + 0] - 5.f;
        float y = (float)gS[(b * SAI + tid) * 2 + 1] - 5.f;
        sm->Dist[tid] = sqrtf(x * x + y * y);
    }
#pragma unroll
    for (int i = 0; i < 4; i++)
        sm->Dsm[tid + i * 256] = gD[b * HWN + tid + i * 256];
#pragma unroll
    for (int i = 0; i < 4; i++) {
        int idx = tid + i * 256;
        int c = idx >> 4, q = idx & 15;
        sm->Qsm[c][q] = gQ[(b * CKD + c) * HWN + hw0 + q];
    }

    // prologue: A loads K chunk0; B loads V chunks 0,1
    if (isA) {
        const float* kb = gK + (size_t)b * CKD * HWN;
#pragma unroll
        for (int j = 0; j < 8; j++) {
            int fi = tid + j * 128;
            int c = fi >> 4, k4 = (fi & 15) * 4;
            cpa16(&sm->Ks[0][c][k4], kb + (size_t)c * HWN + k4);
        }
        asm volatile("cp.async.commit_group;");
    } else {
#pragma unroll
        for (int cc = 0; cc < 2; cc++) {
            const float* vb = gV + (size_t)b * CVD * HWN + cc * KC;
#pragma unroll
            for (int j = 0; j < 8; j++) {
                int fi = ut + j * 128;
                int c = fi >> 4, k4 = (fi & 15) * 4;
                cpa16(&sm->Vs[cc][c][k4], vb + (size_t)c * HWN + k4);
            }
            asm volatile("cp.async.commit_group;");
        }
    }
    __syncthreads();

    if (isA) {
        // ==================== group A: QK + exp ====================
        float lrun[4] = {0.f, 0.f, 0.f, 0.f};

        for (int i = 0; i < NCHUNK; i++) {
            nbar_sync(BID_GRPA, 128);   // WAR: A done reading slot (i+1)&1

            {   // prefetch K(i+1), clamped
                int pn = (i + 1 < NCHUNK) ? i + 1 : NCHUNK - 1;
                int slot = (i + 1) & 1;
                const float* kb = gK + ((size_t)((pn >> 4) * NB + b) * CKD) * HWN + (pn & 15) * KC;
#pragma unroll
                for (int j = 0; j < 8; j++) {
                    int fi = tid + j * 128;
                    int c = fi >> 4, k4 = (fi & 15) * 4;
                    cpa16(&sm->Ks[slot][c][k4], kb + (size_t)c * HWN + k4);
                }
                asm volatile("cp.async.commit_group;");
            }
            asm volatile("cp.async.wait_group 1;");
            nbar_sync(BID_GRPA, 128);   // K(i) visible

            const int s    = i >> 4;
            const int hwb  = (i & 15) * KC;
            const int kbuf = i & 1;
            const int st   = i & 1;

            float dist = sm->Dist[s];
            float2 dd = *reinterpret_cast<const float2*>(&sm->Dsm[hwb + k0]);
            bool kp0 = fabsf(dist * dd.x) > 0.5f;
            bool kp1 = fabsf(dist * dd.y) > 0.5f;

            float2 s2[4];
#pragma unroll
            for (int qi = 0; qi < 4; qi++) s2[qi] = make_float2(0.f, 0.f);
#pragma unroll 8
            for (int c = 0; c < CKD; c++) {
                float2 kv = *reinterpret_cast<const float2*>(&sm->Ks[kbuf][c][k0]);
                float4 qv = *reinterpret_cast<const float4*>(&sm->Qsm[c][q0]);
                s2[0] = ffma2(make_float2(qv.x, qv.x), kv, s2[0]);
                s2[1] = ffma2(make_float2(qv.y, qv.y), kv, s2[1]);
                s2[2] = ffma2(make_float2(qv.z, qv.z), kv, s2[2]);
                s2[3] = ffma2(make_float2(qv.w, qv.w), kv, s2[3]);
            }

            float p[4][2];
#pragma unroll
            for (int qi = 0; qi < 4; qi++) {
                p[qi][0] = kp0 ? __expf(s2[qi].x) : 0.f;
                p[qi][1] = kp1 ? __expf(s2[qi].y) : 0.f;
                lrun[qi] += p[qi][0] + p[qi][1];
            }

            if (i >= 2) nbar_sync(BID_FREE0 + st, 256);
#pragma unroll
            for (int qi = 0; qi < 4; qi++)
                *reinterpret_cast<float2*>(&sm->Ps[st][q0 + qi][k0]) =
                    make_float2(p[qi][0], p[qi][1]);
            nbar_arrive(BID_READY0 + st, 256);
        }

        // reduce l over kg (lane bits 2,3,4)
#pragma unroll
        for (int qi = 0; qi < 4; qi++) {
            lrun[qi] += __shfl_xor_sync(0xffffffffu, lrun[qi], 4);
            lrun[qi] += __shfl_xor_sync(0xffffffffu, lrun[qi], 8);
            lrun[qi] += __shfl_xor_sync(0xffffffffu, lrun[qi], 16);
        }
        if (kg == 0)
            *reinterpret_cast<float4*>(&sm->Lpart[w][qg][0]) =
                make_float4(lrun[0], lrun[1], lrun[2], lrun[3]);

        __syncthreads();   // pairs with B's first epilogue sync
        if (w == 0 && kg == 0) {
            float4 lx = *reinterpret_cast<const float4*>(&sm->Lpart[0][qg][0]);
#pragma unroll
            for (int ww = 1; ww < 4; ww++) {
                float4 t = *reinterpret_cast<const float4*>(&sm->Lpart[ww][qg][0]);
                lx.x += t.x; lx.y += t.y; lx.z += t.z; lx.w += t.w;
            }
            *reinterpret_cast<float4*>(&sm->Lb[q0]) = lx;
        }
        __syncthreads();   // pairs with B's second epilogue sync
    } else {
        // ==================== group B: AV ====================
        float2 acc[4][4];
#pragma unroll
        for (int qi = 0; qi < 4; qi++)
#pragma unroll
            for (int ci = 0; ci < 4; ci++) acc[qi][ci] = make_float2(0.f, 0.f);

        for (int j = 0; j < NCHUNK; j++) {
            nbar_sync(BID_GRPB, 128);   // WAR: B done reading slot (j+2)%3

            {   // prefetch V(j+2), clamped
                int pn = (j + 2 < NCHUNK) ? j + 2 : NCHUNK - 1;
                int slot = (j + 2) % 3;
                const float* vb = gV + ((size_t)((pn >> 4) * NB + b) * CVD) * HWN + (pn & 15) * KC;
#pragma unroll
                for (int jj = 0; jj < 8; jj++) {
                    int fi = ut + jj * 128;
                    int c = fi >> 4, k4 = (fi & 15) * 4;
                    cpa16(&sm->Vs[slot][c][k4], vb + (size_t)c * HWN + k4);
                }
                asm volatile("cp.async.commit_group;");
            }
            asm volatile("cp.async.wait_group 2;");
            nbar_sync(BID_GRPB, 128);

            const int st    = j & 1;
            const int vslot = j % 3;

            nbar_sync(BID_READY0 + st, 256);  // Ps[st] (chunk j) ready

            const float* Pp0 = &sm->Ps[st][q0a + 0][kh * 32];
            const float* Pp1 = &sm->Ps[st][q0a + 1][kh * 32];
            const float* Pp2 = &sm->Ps[st][q0a + 2][kh * 32];
            const float* Pp3 = &sm->Ps[st][q0a + 3][kh * 32];
            const float* Vp0 = &sm->Vs[vslot][cg     ][kh * 32];
            const float* Vp1 = &sm->Vs[vslot][cg + 16][kh * 32];
            const float* Vp2 = &sm->Vs[vslot][cg + 32][kh * 32];
            const float* Vp3 = &sm->Vs[vslot][cg + 48][kh * 32];

#pragma unroll
            for (int t = 0; t < 8; t++) {
                int fo = t * 4;
                float4 p0 = *reinterpret_cast<const float4*>(Pp0 + fo);
                float4 p1 = *reinterpret_cast<const float4*>(Pp1 + fo);
                float4 p2 = *reinterpret_cast<const float4*>(Pp2 + fo);
                float4 p3 = *reinterpret_cast<const float4*>(Pp3 + fo);
                float4 v0 = *reinterpret_cast<const float4*>(Vp0 + fo);
                float4 v1 = *reinterpret_cast<const float4*>(Vp1 + fo);
                float4 v2 = *reinterpret_cast<const float4*>(Vp2 + fo);
                float4 v3 = *reinterpret_cast<const float4*>(Vp3 + fo);
                float2 pl, vl;
#define AVSTEP(qi, P, ci, V) \
                pl = make_float2(P.x, P.y); vl = make_float2(V.x, V.y); \
                acc[qi][ci] = ffma2(pl, vl, acc[qi][ci]); \
                pl = make_float2(P.z, P.w); vl = make_float2(V.z, V.w); \
                acc[qi][ci] = ffma2(pl, vl, acc[qi][ci]);
                AVSTEP(0, p0, 0, v0) AVSTEP(0, p0, 1, v1) AVSTEP(0, p0, 2, v2) AVSTEP(0, p0, 3, v3)
                AVSTEP(1, p1, 0, v0) AVSTEP(1, p1, 1, v1) AVSTEP(1, p1, 2, v2) AVSTEP(1, p1, 3, v3)
                AVSTEP(2, p2, 0, v0) AVSTEP(2, p2, 1, v1) AVSTEP(2, p2, 2, v2) AVSTEP(2, p2, 3, v3)
                AVSTEP(3, p3, 0, v0) AVSTEP(3, p3, 1, v1) AVSTEP(3, p3, 2, v2) AVSTEP(3, p3, 3, v3)
#undef AVSTEP
            }

            nbar_arrive(BID_FREE0 + st, 256);
        }

        __syncthreads();   // all P reads done; Lpart visible
        if (kh == 1) {
#pragma unroll
            for (int qi = 0; qi < 4; qi++)
#pragma unroll
                for (int ci = 0; ci < 4; ci++)
                    sm->Obuf[ul][qi * 4 + ci] = acc[qi][ci];
        }
        __syncthreads();   // Lb + Obuf visible
        if (kh == 0) {
#pragma unroll
            for (int qi = 0; qi < 4; qi++) {
                float linv = 1.f / sm->Lb[q0a + qi];
#pragma unroll
                for (int ci = 0; ci < 4; ci++) {
                    float2 o2 = sm->Obuf[ul][qi * 4 + ci];
                    float o = ((acc[qi][ci].x + o2.x) + (acc[qi][ci].y + o2.y)) * linv;
                    int c = cg + ci * 16;
                    gO[((size_t)b * CVD + c) * HWN + hw0 + q0a + qi] = o;
                }
            }
        }
    }
}

extern "C" void kernel_launch(void* const* d_in, const int* in_sizes, int n_in,
                              void* d_out, int out_size)
{
    const float* gK = (const float*)d_in[0];  // memory_keys   (9,4,64,32,32)
    const float* gV = (const float*)d_in[1];  // memory_values (9,4,64,32,32)
    const float* gQ = (const float*)d_in[2];  // query_query   (4,64,32,32)
    const float* gD = (const float*)d_in[3];  // disparity     (4,1,32,32)
    const int*   gS = (const int*)d_in[4];    // sequence_index(4,9,2)
    float* gO = (float*)d_out;                // (4,64,32,32)

    cudaFuncSetAttribute(cfa_kernel, cudaFuncAttributeMaxDynamicSharedMemorySize,
                         (int)sizeof(Smem));
    dim3 grid(HWN / QT, NB);
    cfa_kernel<<<grid, 256, sizeof(Smem)>>>(gK, gV, gQ, gD, gS, gO);
}

// round 7
// speedup vs baseline: 1.1396x; 1.1396x over previous
#include <cuda_runtime.h>
#include <cfloat>
#include <math.h>

// CrossFrameAttention: B=4, SAI=9, CK=CV=64, H=W=32
// out[b,c,hw] = softmax_k( Q[b,:,hw]·K[b,:,k] + bias[b,k] ) · V[b,k,:]
// keep(k) = |dist(b,s)*disp(b,hw_k)| > 0.5 ; p = keep ? exp(s) : 0 (static-max safe)
//
// 512 threads, QT=32, KC=128, 72 chunks. Warps 0-7 (A): QK+exp; warps 8-15 (B):
// AV with broadcast-friendly 4q x 4c x 64k tiles (conflict-free LDS.64).

#define SAI 9
#define NB 4
#define CKD 64
#define HWN 1024
#define CVD 64
#define QT 32
#define KC 128
#define NCHUNK 72
#define VSTR 132
#define PSTR 132

#define BID_READY0 1
#define BID_READY1 2
#define BID_FREE0  3
#define BID_FREE1  4
#define BID_GRPA   5
#define BID_GRPB   6

struct __align__(16) Smem {
    float Qsm[CKD][QT];           //  8 KB
    float Ks[2][CKD][KC];         // 64 KB  (K 2-stage, A-owned)
    float Vs[3][CVD][VSTR];       // ~101 KB (V 3-stage, B-owned)
    union {
        float  Ps[2][QT][PSTR];   // ~34 KB (P 2-stage)
        float  Obuf[4][32][16];   //  8 KB  epilogue k-half combine
    };
    float Dsm[HWN];               //  4 KB
    float Lpart[8][8][4];
    float Dist[16];
    float Lb[QT];
};

__device__ __forceinline__ float2 ffma2(float2 a, float2 b, float2 c) {
    float2 d;
    asm("fma.rn.f32x2 %0, %1, %2, %3;"
        : "=l"(reinterpret_cast<unsigned long long &>(d))
        : "l"(reinterpret_cast<unsigned long long &>(a)),
          "l"(reinterpret_cast<unsigned long long &>(b)),
          "l"(reinterpret_cast<unsigned long long &>(c)));
    return d;
}

__device__ __forceinline__ void cpa16(const void* dst, const void* src) {
    unsigned d = (unsigned)__cvta_generic_to_shared(dst);
    asm volatile("cp.async.cg.shared.global [%0], [%1], 16;" :: "r"(d), "l"(src));
}

__device__ __forceinline__ void nbar_sync(int id, int cnt) {
    asm volatile("bar.sync %0, %1;" :: "r"(id), "r"(cnt) : "memory");
}
__device__ __forceinline__ void nbar_arrive(int id, int cnt) {
    asm volatile("bar.arrive %0, %1;" :: "r"(id), "r"(cnt) : "memory");
}

__global__ __launch_bounds__(512, 1)
void cfa_kernel(const float* __restrict__ gK, const float* __restrict__ gV,
                const float* __restrict__ gQ, const float* __restrict__ gD,
                const int*   __restrict__ gS, float* __restrict__ gO)
{
    extern __shared__ char raw[];
    Smem* sm = reinterpret_cast<Smem*>(raw);

    const int b   = blockIdx.y;
    const int hw0 = blockIdx.x * QT;
    const int tid = threadIdx.x;
    const bool isA = tid < 256;

    // A mapping: warp w owns keys [16w,16w+16); lane = qg + 8*kg2
    const int lane = tid & 31;
    const int w    = tid >> 5;
    const int qg   = lane & 7;
    const int kg2  = lane >> 3;
    const int q0   = qg * 4;
    const int k0   = w * 16 + kg2 * 4;

    // B mapping: warp wb = (c-quarter ch: 4) x (k-half ksB: 2)
    //            lane = qb(8, bits 0-2) + 8*cb(4, bits 3-4)
    const int ut  = tid & 255;
    const int wb  = ut >> 5;             // 0..7
    const int ch  = wb >> 1;             // c-quarter
    const int ksB = wb & 1;              // k-half
    const int qb  = lane & 7;
    const int cbb = lane >> 3;           // 0..3

    if (tid < SAI) {
        float x = (float)gS[(b * SAI + tid) * 2 + 0] - 5.f;
        float y = (float)gS[(b * SAI + tid) * 2 + 1] - 5.f;
        sm->Dist[tid] = sqrtf(x * x + y * y);
    }
#pragma unroll
    for (int i = 0; i < 2; i++)
        sm->Dsm[tid + i * 512] = gD[b * HWN + tid + i * 512];
#pragma unroll
    for (int i = 0; i < 4; i++) {
        int idx = tid + i * 512;
        sm->Qsm[idx >> 5][idx & 31] = gQ[(b * CKD + (idx >> 5)) * HWN + hw0 + (idx & 31)];
    }

    // prologue: A loads K0 (1 group); B loads V0,V1 (2 groups)
    if (isA) {
        const float* kb = gK + (size_t)b * CKD * HWN;
#pragma unroll
        for (int j = 0; j < 8; j++) {
            int fi = tid + j * 256;
            int c = fi >> 5, k4 = (fi & 31) * 4;
            cpa16(&sm->Ks[0][c][k4], kb + (size_t)c * HWN + k4);
        }
        asm volatile("cp.async.commit_group;");
    } else {
#pragma unroll
        for (int cc = 0; cc < 2; cc++) {
            const float* vb = gV + (size_t)b * CVD * HWN + cc * KC;
#pragma unroll
            for (int j = 0; j < 8; j++) {
                int fi = ut + j * 256;
                int c = fi >> 5, k4 = (fi & 31) * 4;
                cpa16(&sm->Vs[cc][c][k4], vb + (size_t)c * HWN + k4);
            }
            asm volatile("cp.async.commit_group;");
        }
    }
    __syncthreads();

    if (isA) {
        // ==================== group A: QK + exp ====================
        float lrun[4] = {0.f, 0.f, 0.f, 0.f};

        for (int i = 0; i < NCHUNK; i++) {
            nbar_sync(BID_GRPA, 256);   // WAR on K slot (i+1)&1

            {   // prefetch K(i+1), clamped
                int pn = (i + 1 < NCHUNK) ? i + 1 : NCHUNK - 1;
                int slot = (i + 1) & 1;
                const float* kb = gK + ((size_t)((pn >> 3) * NB + b) * CKD) * HWN + (pn & 7) * KC;
#pragma unroll
                for (int j = 0; j < 8; j++) {
                    int fi = tid + j * 256;
                    int c = fi >> 5, k4 = (fi & 31) * 4;
                    cpa16(&sm->Ks[slot][c][k4], kb + (size_t)c * HWN + k4);
                }
                asm volatile("cp.async.commit_group;");
            }
            asm volatile("cp.async.wait_group 1;");
            nbar_sync(BID_GRPA, 256);   // K(i) visible

            const int s    = i >> 3;
            const int hwb  = (i & 7) * KC;
            const int kbuf = i & 1;
            const int st   = i & 1;

            float dist = sm->Dist[s];
            float4 dd = *reinterpret_cast<const float4*>(&sm->Dsm[hwb + k0]);
            bool kp0 = fabsf(dist * dd.x) > 0.5f;
            bool kp1 = fabsf(dist * dd.y) > 0.5f;
            bool kp2 = fabsf(dist * dd.z) > 0.5f;
            bool kp3 = fabsf(dist * dd.w) > 0.5f;

            float2 s2[4][2];
#pragma unroll
            for (int qi = 0; qi < 4; qi++) { s2[qi][0] = make_float2(0.f, 0.f); s2[qi][1] = make_float2(0.f, 0.f); }
#pragma unroll 8
            for (int c = 0; c < CKD; c++) {
                float4 kv = *reinterpret_cast<const float4*>(&sm->Ks[kbuf][c][k0]);
                float4 qv = *reinterpret_cast<const float4*>(&sm->Qsm[c][q0]);
                float2 klo = make_float2(kv.x, kv.y), khi = make_float2(kv.z, kv.w);
                s2[0][0] = ffma2(make_float2(qv.x, qv.x), klo, s2[0][0]);
                s2[0][1] = ffma2(make_float2(qv.x, qv.x), khi, s2[0][1]);
                s2[1][0] = ffma2(make_float2(qv.y, qv.y), klo, s2[1][0]);
                s2[1][1] = ffma2(make_float2(qv.y, qv.y), khi, s2[1][1]);
                s2[2][0] = ffma2(make_float2(qv.z, qv.z), klo, s2[2][0]);
                s2[2][1] = ffma2(make_float2(qv.z, qv.z), khi, s2[2][1]);
                s2[3][0] = ffma2(make_float2(qv.w, qv.w), klo, s2[3][0]);
                s2[3][1] = ffma2(make_float2(qv.w, qv.w), khi, s2[3][1]);
            }

            float p[4][4];
#pragma unroll
            for (int qi = 0; qi < 4; qi++) {
                p[qi][0] = kp0 ? __expf(s2[qi][0].x) : 0.f;
                p[qi][1] = kp1 ? __expf(s2[qi][0].y) : 0.f;
                p[qi][2] = kp2 ? __expf(s2[qi][1].x) : 0.f;
                p[qi][3] = kp3 ? __expf(s2[qi][1].y) : 0.f;
                lrun[qi] += (p[qi][0] + p[qi][1]) + (p[qi][2] + p[qi][3]);
            }

            if (i >= 2) nbar_sync(BID_FREE0 + st, 512);
#pragma unroll
            for (int qi = 0; qi < 4; qi++)
                *reinterpret_cast<float4*>(&sm->Ps[st][q0 + qi][k0]) =
                    make_float4(p[qi][0], p[qi][1], p[qi][2], p[qi][3]);
            nbar_arrive(BID_READY0 + st, 512);
        }

#pragma unroll
        for (int qi = 0; qi < 4; qi++) {
            lrun[qi] += __shfl_xor_sync(0xffffffffu, lrun[qi], 8);
            lrun[qi] += __shfl_xor_sync(0xffffffffu, lrun[qi], 16);
        }
        if (kg2 == 0)
            *reinterpret_cast<float4*>(&sm->Lpart[w][qg][0]) =
                make_float4(lrun[0], lrun[1], lrun[2], lrun[3]);

        __syncthreads();   // pairs with B's first epilogue sync
        if (w == 0 && kg2 == 0) {
            float4 lx = *reinterpret_cast<const float4*>(&sm->Lpart[0][qg][0]);
#pragma unroll
            for (int ww = 1; ww < 8; ww++) {
                float4 t = *reinterpret_cast<const float4*>(&sm->Lpart[ww][qg][0]);
                lx.x += t.x; lx.y += t.y; lx.z += t.z; lx.w += t.w;
            }
            *reinterpret_cast<float4*>(&sm->Lb[q0]) = lx;
        }
        __syncthreads();   // pairs with B's second epilogue sync
    } else {
        // ==================== group B: AV (4q x 4c x 64k tiles) ====================
        float2 acc2[4][4];   // [qi][ci], .x=k-even, .y=k-odd partials
#pragma unroll
        for (int qi = 0; qi < 4; qi++)
#pragma unroll
            for (int ci = 0; ci < 4; ci++) acc2[qi][ci] = make_float2(0.f, 0.f);

        for (int j = 0; j < NCHUNK; j++) {
            nbar_sync(BID_GRPB, 256);   // WAR: B done reading V slot (j+2)%3

            {   // prefetch V(j+2), clamped
                int pn = (j + 2 < NCHUNK) ? j + 2 : NCHUNK - 1;
                int slot = (j + 2) % 3;
                const float* vb = gV + ((size_t)((pn >> 3) * NB + b) * CVD) * HWN + (pn & 7) * KC;
#pragma unroll
                for (int jj = 0; jj < 8; jj++) {
                    int fi = ut + jj * 256;
                    int c = fi >> 5, k4 = (fi & 31) * 4;
                    cpa16(&sm->Vs[slot][c][k4], vb + (size_t)c * HWN + k4);
                }
                asm volatile("cp.async.commit_group;");
            }
            asm volatile("cp.async.wait_group 2;");
            nbar_sync(BID_GRPB, 256);

            const int st    = j & 1;
            const int vslot = j % 3;

            nbar_sync(BID_READY0 + st, 512);  // Ps[st] (chunk j) ready

            // row pointers: q rows qb+8*qi (bank-stride 4 over qb -> conflict-free,
            // cb is broadcast); c rows ch*16+ci*4+cb (bank-stride 4 over cb, qb bcast)
            const float* Pp0 = &sm->Ps[st][qb     ][ksB * 64];
            const float* Pp1 = &sm->Ps[st][qb +  8][ksB * 64];
            const float* Pp2 = &sm->Ps[st][qb + 16][ksB * 64];
            const float* Pp3 = &sm->Ps[st][qb + 24][ksB * 64];
            const int cbase = ch * 16 + cbb;
            const float* Vp0 = &sm->Vs[vslot][cbase     ][ksB * 64];
            const float* Vp1 = &sm->Vs[vslot][cbase +  4][ksB * 64];
            const float* Vp2 = &sm->Vs[vslot][cbase +  8][ksB * 64];
            const float* Vp3 = &sm->Vs[vslot][cbase + 12][ksB * 64];

#pragma unroll 4
            for (int kp = 0; kp < 32; kp++) {
                const int off = kp * 2;
                float2 p0 = *reinterpret_cast<const float2*>(Pp0 + off);
                float2 p1 = *reinterpret_cast<const float2*>(Pp1 + off);
                float2 p2 = *reinterpret_cast<const float2*>(Pp2 + off);
                float2 p3 = *reinterpret_cast<const float2*>(Pp3 + off);
                float2 v0 = *reinterpret_cast<const float2*>(Vp0 + off);
                float2 v1 = *reinterpret_cast<const float2*>(Vp1 + off);
                float2 v2 = *reinterpret_cast<const float2*>(Vp2 + off);
                float2 v3 = *reinterpret_cast<const float2*>(Vp3 + off);
                acc2[0][0] = ffma2(p0, v0, acc2[0][0]);
                acc2[0][1] = ffma2(p0, v1, acc2[0][1]);
                acc2[0][2] = ffma2(p0, v2, acc2[0][2]);
                acc2[0][3] = ffma2(p0, v3, acc2[0][3]);
                acc2[1][0] = ffma2(p1, v0, acc2[1][0]);
                acc2[1][1] = ffma2(p1, v1, acc2[1][1]);
                acc2[1][2] = ffma2(p1, v2, acc2[1][2]);
                acc2[1][3] = ffma2(p1, v3, acc2[1][3]);
                acc2[2][0] = ffma2(p2, v0, acc2[2][0]);
                acc2[2][1] = ffma2(p2, v1, acc2[2][1]);
                acc2[2][2] = ffma2(p2, v2, acc2[2][2]);
                acc2[2][3] = ffma2(p2, v3, acc2[2][3]);
                acc2[3][0] = ffma2(p3, v0, acc2[3][0]);
                acc2[3][1] = ffma2(p3, v1, acc2[3][1]);
                acc2[3][2] = ffma2(p3, v2, acc2[3][2]);
                acc2[3][3] = ffma2(p3, v3, acc2[3][3]);
            }

            nbar_arrive(BID_FREE0 + st, 512);
        }

        __syncthreads();   // all P reads done; Lpart visible (Obuf aliases Ps)
        if (ksB == 1) {
#pragma unroll
            for (int qi = 0; qi < 4; qi++)
#pragma unroll
                for (int ci = 0; ci < 4; ci++)
                    sm->Obuf[ch][lane][qi * 4 + ci] = acc2[qi][ci].x + acc2[qi][ci].y;
        }
        __syncthreads();   // Lb + Obuf visible
        if (ksB == 0) {
#pragma unroll
            for (int qi = 0; qi < 4; qi++) {
                const int q = qb + 8 * qi;
                float linv = 1.f / sm->Lb[q];
#pragma unroll
                for (int ci = 0; ci < 4; ci++) {
                    float o = (acc2[qi][ci].x + acc2[qi][ci].y) + sm->Obuf[ch][lane][qi * 4 + ci];
                    o *= linv;
                    const int c = ch * 16 + ci * 4 + cbb;
                    gO[((size_t)b * CVD + c) * HWN + hw0 + q] = o;
                }
            }
        }
    }
}

extern "C" void kernel_launch(void* const* d_in, const int* in_sizes, int n_in,
                              void* d_out, int out_size)
{
    const float* gK = (const float*)d_in[0];  // memory_keys   (9,4,64,32,32)
    const float* gV = (const float*)d_in[1];  // memory_values (9,4,64,32,32)
    const float* gQ = (const float*)d_in[2];  // query_query   (4,64,32,32)
    const float* gD = (const float*)d_in[3];  // disparity     (4,1,32,32)
    const int*   gS = (const int*)d_in[4];    // sequence_index(4,9,2)
    float* gO = (float*)d_out;                // (4,64,32,32)

    cudaFuncSetAttribute(cfa_kernel, cudaFuncAttributeMaxDynamicSharedMemorySize,
                         (int)sizeof(Smem));
    dim3 grid(HWN / QT, NB);
    cfa_kernel<<<grid, 512, sizeof(Smem)>>>(gK, gV, gQ, gD, gS, gO);
}

// round 8
// speedup vs baseline: 1.1399x; 1.0003x over previous
#include <cuda_runtime.h>
#include <cfloat>
#include <math.h>

// CrossFrameAttention: B=4, SAI=9, CK=CV=64, H=W=32
// out[b,c,hw] = softmax_k( Q[b,:,hw]·K[b,:,k] + bias[b,k] ) · V[b,k,:]
// keep(k) = |dist(b,s)*disp(b,hw_k)| > 0.5 ; p = keep ? exp(s) : 0 (static-max safe)
//
// 512 threads, QT=32, KC=128, 72 chunks. Warps 0-7 (A): QK+exp; warps 8-15 (B):
// AV with broadcast-friendly 4q x 4c x 64k tiles (conflict-free LDS.64).

#define SAI 9
#define NB 4
#define CKD 64
#define HWN 1024
#define CVD 64
#define QT 32
#define KC 128
#define NCHUNK 72
#define VSTR 132
#define PSTR 132

#define BID_READY0 1
#define BID_READY1 2
#define BID_FREE0  3
#define BID_FREE1  4
#define BID_GRPA   5
#define BID_GRPB   6

struct __align__(16) Smem {
    float Qsm[CKD][QT];           //  8 KB
    float Ks[2][CKD][KC];         // 64 KB  (K 2-stage, A-owned)
    float Vs[3][CVD][VSTR];       // ~101 KB (V 3-stage, B-owned)
    union {
        float  Ps[2][QT][PSTR];   // ~34 KB (P 2-stage)
        float  Obuf[4][32][16];   //  8 KB  epilogue k-half combine
    };
    float Dsm[HWN];               //  4 KB
    float Lpart[8][8][4];
    float Dist[16];
    float Lb[QT];
};

__device__ __forceinline__ float2 ffma2(float2 a, float2 b, float2 c) {
    float2 d;
    asm("fma.rn.f32x2 %0, %1, %2, %3;"
        : "=l"(reinterpret_cast<unsigned long long &>(d))
        : "l"(reinterpret_cast<unsigned long long &>(a)),
          "l"(reinterpret_cast<unsigned long long &>(b)),
          "l"(reinterpret_cast<unsigned long long &>(c)));
    return d;
}

__device__ __forceinline__ void cpa16(const void* dst, const void* src) {
    unsigned d = (unsigned)__cvta_generic_to_shared(dst);
    asm volatile("cp.async.cg.shared.global [%0], [%1], 16;" :: "r"(d), "l"(src));
}

__device__ __forceinline__ void nbar_sync(int id, int cnt) {
    asm volatile("bar.sync %0, %1;" :: "r"(id), "r"(cnt) : "memory");
}
__device__ __forceinline__ void nbar_arrive(int id, int cnt) {
    asm volatile("bar.arrive %0, %1;" :: "r"(id), "r"(cnt) : "memory");
}

__global__ __launch_bounds__(512, 1)
void cfa_kernel(const float* __restrict__ gK, const float* __restrict__ gV,
                const float* __restrict__ gQ, const float* __restrict__ gD,
                const int*   __restrict__ gS, float* __restrict__ gO)
{
    extern __shared__ char raw[];
    Smem* sm = reinterpret_cast<Smem*>(raw);

    const int b   = blockIdx.y;
    const int hw0 = blockIdx.x * QT;
    const int tid = threadIdx.x;
    const bool isA = tid < 256;

    // A mapping: warp w owns keys [16w,16w+16); lane = qg + 8*kg2
    const int lane = tid & 31;
    const int w    = tid >> 5;
    const int qg   = lane & 7;
    const int kg2  = lane >> 3;
    const int q0   = qg * 4;
    const int k0   = w * 16 + kg2 * 4;

    // B mapping: warp wb = (c-quarter ch: 4) x (k-half ksB: 2)
    //            lane = qb(8, bits 0-2) + 8*cb(4, bits 3-4)
    const int ut  = tid & 255;
    const int wb  = ut >> 5;             // 0..7
    const int ch  = wb >> 1;             // c-quarter
    const int ksB = wb & 1;              // k-half
    const int qb  = lane & 7;
    const int cbb = lane >> 3;           // 0..3

    if (tid < SAI) {
        float x = (float)gS[(b * SAI + tid) * 2 + 0] - 5.f;
        float y = (float)gS[(b * SAI + tid) * 2 + 1] - 5.f;
        sm->Dist[tid] = sqrtf(x * x + y * y);
    }
#pragma unroll
    for (int i = 0; i < 2; i++)
        sm->Dsm[tid + i * 512] = gD[b * HWN + tid + i * 512];
#pragma unroll
    for (int i = 0; i < 4; i++) {
        int idx = tid + i * 512;
        sm->Qsm[idx >> 5][idx & 31] = gQ[(b * CKD + (idx >> 5)) * HWN + hw0 + (idx & 31)];
    }

    // prologue: A loads K0 (1 group); B loads V0,V1 (2 groups)
    if (isA) {
        const float* kb = gK + (size_t)b * CKD * HWN;
#pragma unroll
        for (int j = 0; j < 8; j++) {
            int fi = tid + j * 256;
            int c = fi >> 5, k4 = (fi & 31) * 4;
            cpa16(&sm->Ks[0][c][k4], kb + (size_t)c * HWN + k4);
        }
        asm volatile("cp.async.commit_group;");
    } else {
#pragma unroll
        for (int cc = 0; cc < 2; cc++) {
            const float* vb = gV + (size_t)b * CVD * HWN + cc * KC;
#pragma unroll
            for (int j = 0; j < 8; j++) {
                int fi = ut + j * 256;
                int c = fi >> 5, k4 = (fi & 31) * 4;
                cpa16(&sm->Vs[cc][c][k4], vb + (size_t)c * HWN + k4);
            }
            asm volatile("cp.async.commit_group;");
        }
    }
    __syncthreads();

    if (isA) {
        // ==================== group A: QK + exp ====================
        float lrun[4] = {0.f, 0.f, 0.f, 0.f};

        for (int i = 0; i < NCHUNK; i++) {
            nbar_sync(BID_GRPA, 256);   // WAR on K slot (i+1)&1

            {   // prefetch K(i+1), clamped
                int pn = (i + 1 < NCHUNK) ? i + 1 : NCHUNK - 1;
                int slot = (i + 1) & 1;
                const float* kb = gK + ((size_t)((pn >> 3) * NB + b) * CKD) * HWN + (pn & 7) * KC;
#pragma unroll
                for (int j = 0; j < 8; j++) {
                    int fi = tid + j * 256;
                    int c = fi >> 5, k4 = (fi & 31) * 4;
                    cpa16(&sm->Ks[slot][c][k4], kb + (size_t)c * HWN + k4);
                }
                asm volatile("cp.async.commit_group;");
            }
            asm volatile("cp.async.wait_group 1;");
            nbar_sync(BID_GRPA, 256);   // K(i) visible

            const int s    = i >> 3;
            const int hwb  = (i & 7) * KC;
            const int kbuf = i & 1;
            const int st   = i & 1;

            float dist = sm->Dist[s];
            float4 dd = *reinterpret_cast<const float4*>(&sm->Dsm[hwb + k0]);
            bool kp0 = fabsf(dist * dd.x) > 0.5f;
            bool kp1 = fabsf(dist * dd.y) > 0.5f;
            bool kp2 = fabsf(dist * dd.z) > 0.5f;
            bool kp3 = fabsf(dist * dd.w) > 0.5f;

            float2 s2[4][2];
#pragma unroll
            for (int qi = 0; qi < 4; qi++) { s2[qi][0] = make_float2(0.f, 0.f); s2[qi][1] = make_float2(0.f, 0.f); }
#pragma unroll 8
            for (int c = 0; c < CKD; c++) {
                float4 kv = *reinterpret_cast<const float4*>(&sm->Ks[kbuf][c][k0]);
                float4 qv = *reinterpret_cast<const float4*>(&sm->Qsm[c][q0]);
                float2 klo = make_float2(kv.x, kv.y), khi = make_float2(kv.z, kv.w);
                s2[0][0] = ffma2(make_float2(qv.x, qv.x), klo, s2[0][0]);
                s2[0][1] = ffma2(make_float2(qv.x, qv.x), khi, s2[0][1]);
                s2[1][0] = ffma2(make_float2(qv.y, qv.y), klo, s2[1][0]);
                s2[1][1] = ffma2(make_float2(qv.y, qv.y), khi, s2[1][1]);
                s2[2][0] = ffma2(make_float2(qv.z, qv.z), klo, s2[2][0]);
                s2[2][1] = ffma2(make_float2(qv.z, qv.z), khi, s2[2][1]);
                s2[3][0] = ffma2(make_float2(qv.w, qv.w), klo, s2[3][0]);
                s2[3][1] = ffma2(make_float2(qv.w, qv.w), khi, s2[3][1]);
            }

            float p[4][4];
#pragma unroll
            for (int qi = 0; qi < 4; qi++) {
                p[qi][0] = kp0 ? __expf(s2[qi][0].x) : 0.f;
                p[qi][1] = kp1 ? __expf(s2[qi][0].y) : 0.f;
                p[qi][2] = kp2 ? __expf(s2[qi][1].x) : 0.f;
                p[qi][3] = kp3 ? __expf(s2[qi][1].y) : 0.f;
                lrun[qi] += (p[qi][0] + p[qi][1]) + (p[qi][2] + p[qi][3]);
            }

            if (i >= 2) nbar_sync(BID_FREE0 + st, 512);
#pragma unroll
            for (int qi = 0; qi < 4; qi++)
                *reinterpret_cast<float4*>(&sm->Ps[st][q0 + qi][k0]) =
                    make_float4(p[qi][0], p[qi][1], p[qi][2], p[qi][3]);
            nbar_arrive(BID_READY0 + st, 512);
        }

#pragma unroll
        for (int qi = 0; qi < 4; qi++) {
            lrun[qi] += __shfl_xor_sync(0xffffffffu, lrun[qi], 8);
            lrun[qi] += __shfl_xor_sync(0xffffffffu, lrun[qi], 16);
        }
        if (kg2 == 0)
            *reinterpret_cast<float4*>(&sm->Lpart[w][qg][0]) =
                make_float4(lrun[0], lrun[1], lrun[2], lrun[3]);

        __syncthreads();   // pairs with B's first epilogue sync
        if (w == 0 && kg2 == 0) {
            float4 lx = *reinterpret_cast<const float4*>(&sm->Lpart[0][qg][0]);
#pragma unroll
            for (int ww = 1; ww < 8; ww++) {
                float4 t = *reinterpret_cast<const float4*>(&sm->Lpart[ww][qg][0]);
                lx.x += t.x; lx.y += t.y; lx.z += t.z; lx.w += t.w;
            }
            *reinterpret_cast<float4*>(&sm->Lb[q0]) = lx;
        }
        __syncthreads();   // pairs with B's second epilogue sync
    } else {
        // ==================== group B: AV (4q x 4c x 64k tiles) ====================
        float2 acc2[4][4];   // [qi][ci], .x=k-even, .y=k-odd partials
#pragma unroll
        for (int qi = 0; qi < 4; qi++)
#pragma unroll
            for (int ci = 0; ci < 4; ci++) acc2[qi][ci] = make_float2(0.f, 0.f);

        for (int j = 0; j < NCHUNK; j++) {
            nbar_sync(BID_GRPB, 256);   // WAR: B done reading V slot (j+2)%3

            {   // prefetch V(j+2), clamped
                int pn = (j + 2 < NCHUNK) ? j + 2 : NCHUNK - 1;
                int slot = (j + 2) % 3;
                const float* vb = gV + ((size_t)((pn >> 3) * NB + b) * CVD) * HWN + (pn & 7) * KC;
#pragma unroll
                for (int jj = 0; jj < 8; jj++) {
                    int fi = ut + jj * 256;
                    int c = fi >> 5, k4 = (fi & 31) * 4;
                    cpa16(&sm->Vs[slot][c][k4], vb + (size_t)c * HWN + k4);
                }
                asm volatile("cp.async.commit_group;");
            }
            asm volatile("cp.async.wait_group 2;");
            nbar_sync(BID_GRPB, 256);

            const int st    = j & 1;
            const int vslot = j % 3;

            nbar_sync(BID_READY0 + st, 512);  // Ps[st] (chunk j) ready

            // row pointers: q rows qb+8*qi (bank-stride 4 over qb -> conflict-free,
            // cb is broadcast); c rows ch*16+ci*4+cb (bank-stride 4 over cb, qb bcast)
            const float* Pp0 = &sm->Ps[st][qb     ][ksB * 64];
            const float* Pp1 = &sm->Ps[st][qb +  8][ksB * 64];
            const float* Pp2 = &sm->Ps[st][qb + 16][ksB * 64];
            const float* Pp3 = &sm->Ps[st][qb + 24][ksB * 64];
            const int cbase = ch * 16 + cbb;
            const float* Vp0 = &sm->Vs[vslot][cbase     ][ksB * 64];
            const float* Vp1 = &sm->Vs[vslot][cbase +  4][ksB * 64];
            const float* Vp2 = &sm->Vs[vslot][cbase +  8][ksB * 64];
            const float* Vp3 = &sm->Vs[vslot][cbase + 12][ksB * 64];

#pragma unroll 4
            for (int kp = 0; kp < 32; kp++) {
                const int off = kp * 2;
                float2 p0 = *reinterpret_cast<const float2*>(Pp0 + off);
                float2 p1 = *reinterpret_cast<const float2*>(Pp1 + off);
                float2 p2 = *reinterpret_cast<const float2*>(Pp2 + off);
                float2 p3 = *reinterpret_cast<const float2*>(Pp3 + off);
                float2 v0 = *reinterpret_cast<const float2*>(Vp0 + off);
                float2 v1 = *reinterpret_cast<const float2*>(Vp1 + off);
                float2 v2 = *reinterpret_cast<const float2*>(Vp2 + off);
                float2 v3 = *reinterpret_cast<const float2*>(Vp3 + off);
                acc2[0][0] = ffma2(p0, v0, acc2[0][0]);
                acc2[0][1] = ffma2(p0, v1, acc2[0][1]);
                acc2[0][2] = ffma2(p0, v2, acc2[0][2]);
                acc2[0][3] = ffma2(p0, v3, acc2[0][3]);
                acc2[1][0] = ffma2(p1, v0, acc2[1][0]);
                acc2[1][1] = ffma2(p1, v1, acc2[1][1]);
                acc2[1][2] = ffma2(p1, v2, acc2[1][2]);
                acc2[1][3] = ffma2(p1, v3, acc2[1][3]);
                acc2[2][0] = ffma2(p2, v0, acc2[2][0]);
                acc2[2][1] = ffma2(p2, v1, acc2[2][1]);
                acc2[2][2] = ffma2(p2, v2, acc2[2][2]);
                acc2[2][3] = ffma2(p2, v3, acc2[2][3]);
                acc2[3][0] = ffma2(p3, v0, acc2[3][0]);
                acc2[3][1] = ffma2(p3, v1, acc2[3][1]);
                acc2[3][2] = ffma2(p3, v2, acc2[3][2]);
                acc2[3][3] = ffma2(p3, v3, acc2[3][3]);
            }

            nbar_arrive(BID_FREE0 + st, 512);
        }

        __syncthreads();   // all P reads done; Lpart visible (Obuf aliases Ps)
        if (ksB == 1) {
#pragma unroll
            for (int qi = 0; qi < 4; qi++)
#pragma unroll
                for (int ci = 0; ci < 4; ci++)
                    sm->Obuf[ch][lane][qi * 4 + ci] = acc2[qi][ci].x + acc2[qi][ci].y;
        }
        __syncthreads();   // Lb + Obuf visible
        if (ksB == 0) {
#pragma unroll
            for (int qi = 0; qi < 4; qi++) {
                const int q = qb + 8 * qi;
                float linv = 1.f / sm->Lb[q];
#pragma unroll
                for (int ci = 0; ci < 4; ci++) {
                    float o = (acc2[qi][ci].x + acc2[qi][ci].y) + sm->Obuf[ch][lane][qi * 4 + ci];
                    o *= linv;
                    const int c = ch * 16 + ci * 4 + cbb;
                    gO[((size_t)b * CVD + c) * HWN + hw0 + q] = o;
                }
            }
        }
    }
}

extern "C" void kernel_launch(void* const* d_in, const int* in_sizes, int n_in,
                              void* d_out, int out_size)
{
    const float* gK = (const float*)d_in[0];  // memory_keys   (9,4,64,32,32)
    const float* gV = (const float*)d_in[1];  // memory_values (9,4,64,32,32)
    const float* gQ = (const float*)d_in[2];  // query_query   (4,64,32,32)
    const float* gD = (const float*)d_in[3];  // disparity     (4,1,32,32)
    const int*   gS = (const int*)d_in[4];    // sequence_index(4,9,2)
    float* gO = (float*)d_out;                // (4,64,32,32)

    cudaFuncSetAttribute(cfa_kernel, cudaFuncAttributeMaxDynamicSharedMemorySize,
                         (int)sizeof(Smem));
    dim3 grid(HWN / QT, NB);
    cfa_kernel<<<grid, 512, sizeof(Smem)>>>(gK, gV, gQ, gD, gS, gO);
}

// round 10
// speedup vs baseline: 4.0151x; 3.5223x over previous
#include <cuda_runtime.h>
#include <cuda_bf16.h>
#include <cstdint>
#include <math.h>

// CrossFrameAttention via mma.sync m16n8k16 bf16 (compiles under compute_103;
// tcgen05 is feature-gated off in this toolchain). bf16 hi/lo split (3 GEMM
// combos per product), static-max softmax, split-k over frames.
//   prepass : K fp32 -> bf16 h/l [key][ch] tiles; V -> [ch][key] tiles (pitch 72)
//   cfa_main: per (qtile,b,frame): S = Q*K^T, P = mask*exp(S) (frag-resident),
//             O += P*V; writes partial numerator + denominator
//   reduce_k: out = sum_f num / sum_f den

#define SAI 9
#define NB 4
#define CKD 64
#define HWN 1024
#define NGRP 16
#define NQT 8

#define KP 72              // padded row pitch (bf16 elems)
#define ROWB 144           // row bytes
#define SPLITB 9216        // [64][72] bf16 bytes
#define TILEB 18432        // [2 split][64][72] bf16 bytes

__device__ __align__(16) char g_KT[SAI * NB * NGRP * TILEB];   // 10.6 MB
__device__ __align__(16) char g_VT[SAI * NB * NGRP * TILEB];   // 10.6 MB
__device__ float g_On[SAI * NB * NQT * 64 * 128];              // 9.4 MB
__device__ float g_L [SAI * NB * NQT * 128];

// ---------------- helpers ----------------
__device__ __forceinline__ uint32_t smem_u32(const void* p) {
    uint32_t a;
    asm("{ .reg .u64 t; cvta.to.shared.u64 t, %1; cvt.u32.u64 %0, t; }" : "=r"(a) : "l"(p));
    return a;
}

__device__ __forceinline__ uint32_t cvt2bf(float hi, float lo) {
    uint32_t r;
    asm("cvt.rn.bf16x2.f32 %0, %1, %2;" : "=r"(r) : "f"(hi), "f"(lo));
    return r;   // low 16 bits = bf16(lo), high = bf16(hi)
}

__device__ __forceinline__ void cpa16(void* dst, const void* src) {
    unsigned d = (unsigned)__cvta_generic_to_shared(dst);
    asm volatile("cp.async.cg.shared.global [%0], [%1], 16;" :: "r"(d), "l"(src));
}

__device__ __forceinline__ void ldsm4(uint32_t& r0, uint32_t& r1, uint32_t& r2,
                                      uint32_t& r3, uint32_t addr) {
    asm volatile("ldmatrix.sync.aligned.m8n8.x4.shared.b16 {%0,%1,%2,%3}, [%4];"
                 : "=r"(r0), "=r"(r1), "=r"(r2), "=r"(r3) : "r"(addr));
}

__device__ __forceinline__ void mma16816(float* c, const uint32_t* a,
                                         uint32_t b0, uint32_t b1) {
    asm volatile(
        "mma.sync.aligned.m16n8k16.row.col.f32.bf16.bf16.f32 "
        "{%0,%1,%2,%3}, {%4,%5,%6,%7}, {%8,%9}, {%0,%1,%2,%3};"
        : "+f"(c[0]), "+f"(c[1]), "+f"(c[2]), "+f"(c[3])
        : "r"(a[0]), "r"(a[1]), "r"(a[2]), "r"(a[3]), "r"(b0), "r"(b1));
}

// ---------------- prepass ----------------
// one block per (sb, 64-key group): K -> [key][ch] h/l, V -> [ch][key] h/l
__global__ __launch_bounds__(128)
void prepass(const float* __restrict__ gK, const float* __restrict__ gV)
{
    __shared__ __nv_bfloat16 T[2][64][KP];   // 18432 B, reused K then V

    const int bx = blockIdx.x;
    const int grp = bx & 15, sb = bx >> 4;
    const int hwb = grp * 64;
    const int tid = threadIdx.x;

    // zero padding columns once (stays zero for both passes)
#pragma unroll
    for (int i = 0; i < 8; i++) {
        int idx = tid + i * 128;                 // 1024 pad entries
        int sp = idx >> 9, r = (idx >> 3) & 63, c = 64 + (idx & 7);
        T[sp][r][c] = __float2bfloat16(0.f);
    }

    const float* kb = gK + (size_t)sb * CKD * HWN + hwb;
    const float* vb = gV + (size_t)sb * CKD * HWN + hwb;

    // --- K pass: T[split][key][ch] ---
#pragma unroll
    for (int i = 0; i < 32; i++) {
        int idx = tid + i * 128;                 // 4096 elems
        int c = idx >> 6, k = idx & 63;
        float f = kb[(size_t)c * HWN + k];
        __nv_bfloat16 h = __float2bfloat16(f);
        T[0][k][c] = h;
        T[1][k][c] = __float2bfloat16(f - __bfloat162float(h));
    }
    __syncthreads();
    {
        const uint4* src = (const uint4*)&T[0][0][0];
        uint4* dst = (uint4*)(g_KT + (size_t)bx * TILEB);
#pragma unroll
        for (int i = 0; i < 9; i++) dst[tid + i * 128] = src[tid + i * 128];
    }
    __syncthreads();

    // --- V pass: T[split][ch][key] ---
#pragma unroll
    for (int i = 0; i < 32; i++) {
        int idx = tid + i * 128;
        int c = idx >> 6, k = idx & 63;
        float f = vb[(size_t)c * HWN + k];
        __nv_bfloat16 h = __float2bfloat16(f);
        T[0][c][k] = h;
        T[1][c][k] = __float2bfloat16(f - __bfloat162float(h));
    }
    __syncthreads();
    {
        const uint4* src = (const uint4*)&T[0][0][0];
        uint4* dst = (uint4*)(g_VT + (size_t)bx * TILEB);
#pragma unroll
        for (int i = 0; i < 9; i++) dst[tid + i * 128] = src[tid + i * 128];
    }
}

// ---------------- main ----------------
// smem: [0,4096) Dsm ; [4096,40960) K tiles [2buf][2split][64][72]
//       [40960,77824) V tiles same
#define SM_BYTES 77824

__global__ __launch_bounds__(256, 2)
void cfa_main(const float* __restrict__ gQ, const float* __restrict__ gD,
              const int* __restrict__ gS)
{
    extern __shared__ char raw[];
    float* Dsm = (float*)raw;
    char* Kraw = raw + 4096;
    char* Vraw = raw + 40960;
    const uint32_t sb32 = smem_u32(raw);
    const uint32_t KSB = sb32 + 4096;
    const uint32_t VSB = sb32 + 40960;

    const int qt = blockIdx.x, b = blockIdx.y, s = blockIdx.z;
    const int sb = s * NB + b;
    const int tid = threadIdx.x;
    const int w = tid >> 5, lane = tid & 31;
    const int g = lane >> 2, t = lane & 3;
    const int hw0 = qt * 128;

    // prologue: chunk 0 -> buf 0 (K: bytes [0,18432), V same; 2304 x 16B)
    {
        const char* sk = g_KT + (size_t)(sb * NGRP) * TILEB;
        const char* sv = g_VT + (size_t)(sb * NGRP) * TILEB;
#pragma unroll
        for (int j = 0; j < 9; j++) {
            int idx = tid + j * 256;
            if (idx < 1152) cpa16(Kraw + idx * 16, sk + idx * 16);
            else            cpa16(Vraw + (idx - 1152) * 16, sv + (idx - 1152) * 16);
        }
        asm volatile("cp.async.commit_group;");
    }

    // Dsm + dist
#pragma unroll
    for (int i = 0; i < 4; i++) Dsm[tid + i * 256] = gD[b * HWN + tid + i * 256];
    float ddx = (float)gS[(b * SAI + s) * 2 + 0] - 5.f;
    float ddy = (float)gS[(b * SAI + s) * 2 + 1] - 5.f;
    const float dist = sqrtf(ddx * ddx + ddy * ddy);

    // Q fragments (hi/lo), direct from gmem: warp w owns queries [16w,16w+16)
    uint32_t Qh[4][4], Ql[4][4];
    {
        const float* qp = gQ + (size_t)b * CKD * HWN + hw0;
        const int qa = 16 * w + g;
#pragma unroll
        for (int kk = 0; kk < 4; kk++) {
#pragma unroll
            for (int r = 0; r < 4; r++) {
                int rr = qa + ((r & 1) << 3);            // a1,a3: row+8
                int cc = kk * 16 + 2 * t + ((r & 2) << 2); // a2,a3: k+8
                float f0 = qp[(size_t)cc * HWN + rr];
                float f1 = qp[(size_t)(cc + 1) * HWN + rr];
                uint32_t h = cvt2bf(f1, f0);
                float e0 = f0 - __uint_as_float(h << 16);
                float e1 = f1 - __uint_as_float(h & 0xFFFF0000u);
                Qh[kk][r] = h;
                Ql[kk][r] = cvt2bf(e1, e0);
            }
        }
    }

    // ldmatrix per-lane row/col offset (pitch 144B):
    // lanes 0-7: rows 0-7 col+0 | 8-15: rows 0-7 col+8 | 16-23: rows 8-15 col+0 | 24-31: rows 8-15 col+8
    const uint32_t lrow = (uint32_t)((lane & 7) + ((lane >> 4) << 3)) * ROWB
                        + (uint32_t)(((lane >> 3) & 1) << 4);

    float Oacc[8][4];
#pragma unroll
    for (int j = 0; j < 8; j++)
#pragma unroll
        for (int r = 0; r < 4; r++) Oacc[j][r] = 0.f;
    float lrun0 = 0.f, lrun1 = 0.f;

    __syncthreads();   // Dsm visible

    for (int gc = 0; gc < NGRP; gc++) {
        const int buf = gc & 1;

        __syncthreads();   // all warps done with chunk gc-1 -> buf^1 free

        {   // prefetch chunk gc+1 (clamped dup keeps wait depth uniform)
            int pn = (gc + 1 < NGRP) ? gc + 1 : NGRP - 1;
            int pb = (gc + 1) & 1;
            const char* sk = g_KT + (size_t)(sb * NGRP + pn) * TILEB;
            const char* sv = g_VT + (size_t)(sb * NGRP + pn) * TILEB;
#pragma unroll
            for (int j = 0; j < 9; j++) {
                int idx = tid + j * 256;
                if (idx < 1152) cpa16(Kraw + pb * TILEB + idx * 16, sk + idx * 16);
                else cpa16(Vraw + pb * TILEB + (idx - 1152) * 16, sv + (idx - 1152) * 16);
            }
            asm volatile("cp.async.commit_group;");
        }
        asm volatile("cp.async.wait_group 1;");
        __syncthreads();   // chunk gc visible to all

        // ---- S = Qh*Kh + Qh*Kl + Ql*Kh  (16q x 64k per warp) ----
        float Sacc[8][4];
#pragma unroll
        for (int j = 0; j < 8; j++)
#pragma unroll
            for (int r = 0; r < 4; r++) Sacc[j][r] = 0.f;

        const uint32_t kbase = KSB + buf * TILEB;
#pragma unroll
        for (int kk = 0; kk < 4; kk++) {
#pragma unroll
            for (int np = 0; np < 4; np++) {
                uint32_t ah = kbase + np * (16 * ROWB) + kk * 32 + lrow;
                uint32_t h0, h1, h2, h3, l0, l1, l2, l3;
                ldsm4(h0, h1, h2, h3, ah);
                ldsm4(l0, l1, l2, l3, ah + SPLITB);
                mma16816(Sacc[2 * np],     Qh[kk], h0, h1);
                mma16816(Sacc[2 * np],     Qh[kk], l0, l1);
                mma16816(Sacc[2 * np],     Ql[kk], h0, h1);
                mma16816(Sacc[2 * np + 1], Qh[kk], h2, h3);
                mma16816(Sacc[2 * np + 1], Qh[kk], l2, l3);
                mma16816(Sacc[2 * np + 1], Ql[kk], h2, h3);
            }
        }

        // ---- P = keep ? exp(S) : 0 ; split to bf16 h/l, fragment-resident ----
        uint32_t PhA[8], PhB[8], PlA[8], PlB[8];
        const int hwb = gc * 64;
#pragma unroll
        for (int j = 0; j < 8; j++) {
            int k0 = hwb + 8 * j + 2 * t;
            bool kp0 = fabsf(dist * Dsm[k0])     > 0.5f;
            bool kp1 = fabsf(dist * Dsm[k0 + 1]) > 0.5f;
            float p0 = kp0 ? __expf(Sacc[j][0]) : 0.f;
            float p1 = kp1 ? __expf(Sacc[j][1]) : 0.f;
            float p2 = kp0 ? __expf(Sacc[j][2]) : 0.f;
            float p3 = kp1 ? __expf(Sacc[j][3]) : 0.f;
            lrun0 += p0 + p1;
            lrun1 += p2 + p3;
            uint32_t hA = cvt2bf(p1, p0);
            uint32_t hB = cvt2bf(p3, p2);
            PhA[j] = hA; PhB[j] = hB;
            PlA[j] = cvt2bf(p1 - __uint_as_float(hA & 0xFFFF0000u),
                            p0 - __uint_as_float(hA << 16));
            PlB[j] = cvt2bf(p3 - __uint_as_float(hB & 0xFFFF0000u),
                            p2 - __uint_as_float(hB << 16));
        }

        // ---- O += Ph*Vh + Ph*Vl + Pl*Vh  (16q x 64c per warp) ----
        const uint32_t vbase = VSB + buf * TILEB;
#pragma unroll
        for (int kk = 0; kk < 4; kk++) {
            uint32_t ah[4] = {PhA[2 * kk], PhB[2 * kk], PhA[2 * kk + 1], PhB[2 * kk + 1]};
            uint32_t al[4] = {PlA[2 * kk], PlB[2 * kk], PlA[2 * kk + 1], PlB[2 * kk + 1]};
#pragma unroll
            for (int np = 0; np < 4; np++) {
                uint32_t av = vbase + np * (16 * ROWB) + kk * 32 + lrow;
                uint32_t h0, h1, h2, h3, l0, l1, l2, l3;
                ldsm4(h0, h1, h2, h3, av);
                ldsm4(l0, l1, l2, l3, av + SPLITB);
                mma16816(Oacc[2 * np],     ah, h0, h1);
                mma16816(Oacc[2 * np],     ah, l0, l1);
                mma16816(Oacc[2 * np],     al, h0, h1);
                mma16816(Oacc[2 * np + 1], ah, h2, h3);
                mma16816(Oacc[2 * np + 1], ah, l2, l3);
                mma16816(Oacc[2 * np + 1], al, h2, h3);
            }
        }
    }

    asm volatile("cp.async.wait_group 0;");   // drain dup prefetch before exit

    // ---- epilogue: l reduce within quads; write partials ----
    lrun0 += __shfl_xor_sync(0xffffffffu, lrun0, 1);
    lrun0 += __shfl_xor_sync(0xffffffffu, lrun0, 2);
    lrun1 += __shfl_xor_sync(0xffffffffu, lrun1, 1);
    lrun1 += __shfl_xor_sync(0xffffffffu, lrun1, 2);
    const size_t lb = (size_t)(sb * NQT + qt) * 128;
    if (t == 0) {
        g_L[lb + 16 * w + g]     = lrun0;
        g_L[lb + 16 * w + 8 + g] = lrun1;
    }

    float* on = g_On + (size_t)(sb * NQT + qt) * 8192;   // [c][128 q]
    const int qa = 16 * w + g;
#pragma unroll
    for (int j = 0; j < 8; j++) {
        int c = 8 * j + 2 * t;
        on[(size_t)c * 128 + qa]           = Oacc[j][0];
        on[(size_t)(c + 1) * 128 + qa]     = Oacc[j][1];
        on[(size_t)c * 128 + qa + 8]       = Oacc[j][2];
        on[(size_t)(c + 1) * 128 + qa + 8] = Oacc[j][3];
    }
}

// ---------------- reduce ----------------
__global__ __launch_bounds__(256)
void reduce_k(float* __restrict__ gO)
{
    int idx = blockIdx.x * 256 + threadIdx.x;   // (b*64+c)*1024 + hw
    int b = idx >> 16;
    int c = (idx >> 10) & 63;
    int hw = idx & 1023;
    int qt = hw >> 7, q = hw & 127;
    float num = 0.f, den = 0.f;
#pragma unroll
    for (int s = 0; s < SAI; s++) {
        int sb = s * NB + b;
        num += g_On[(size_t)(sb * NQT + qt) * 8192 + c * 128 + q];
        den += g_L[(size_t)(sb * NQT + qt) * 128 + q];
    }
    gO[idx] = num / den;
}

extern "C" void kernel_launch(void* const* d_in, const int* in_sizes, int n_in,
                              void* d_out, int out_size)
{
    const float* gK = (const float*)d_in[0];  // memory_keys   (9,4,64,32,32)
    const float* gV = (const float*)d_in[1];  // memory_values (9,4,64,32,32)
    const float* gQ = (const float*)d_in[2];  // query_query   (4,64,32,32)
    const float* gD = (const float*)d_in[3];  // disparity     (4,1,32,32)
    const int*   gS = (const int*)d_in[4];    // sequence_index(4,9,2)
    float* gO = (float*)d_out;                // (4,64,32,32)

    cudaFuncSetAttribute(cfa_main, cudaFuncAttributeMaxDynamicSharedMemorySize, SM_BYTES);

    prepass<<<SAI * NB * NGRP, 128>>>(gK, gV);
    dim3 gr(NQT, NB, SAI);
    cfa_main<<<gr, 256, SM_BYTES>>>(gQ, gD, gS);
    reduce_k<<<(NB * 64 * HWN) / 256, 256>>>(gO);
}

// round 11
// speedup vs baseline: 4.0255x; 1.0026x over previous
#include <cuda_runtime.h>
#include <cuda_bf16.h>
#include <cstdint>
#include <math.h>

// CrossFrameAttention via mma.sync m16n8k16 bf16 (tcgen05 is feature-gated off
// under this toolchain's compute_103 PTX target). bf16 hi/lo split (3 combos
// per GEMM), static-max softmax, split-k over frames.
//   prepass : K fp32 -> bf16 h/l [key][ch] tiles (smem transpose);
//             V -> [ch][key] tiles written directly (pitch 72)
//   cfa_main: per (qtile,b,frame): S = Q*K^T, P = mask*exp(S) (frag-resident),
//             O += P*V; 3-buf smem ring, 1 sync/chunk, ballot keep-bitmask
//   reduce_k: out = sum_f num / sum_f den (float4)

#define SAI 9
#define NB 4
#define CKD 64
#define HWN 1024
#define NGRP 16
#define NQT 8

#define KP 72              // padded row pitch (bf16 elems)
#define ROWB 144           // row bytes
#define SPLITB 9216        // [64][72] bf16 bytes
#define TILEB 18432        // [2 split][64][72] bf16 bytes

__device__ __align__(16) char g_KT[SAI * NB * NGRP * TILEB];   // 10.6 MB
__device__ __align__(16) char g_VT[SAI * NB * NGRP * TILEB];   // 10.6 MB
__device__ float g_On[SAI * NB * NQT * 64 * 128];              // 9.4 MB
__device__ float g_L [SAI * NB * NQT * 128];

// ---------------- helpers ----------------
__device__ __forceinline__ uint32_t smem_u32(const void* p) {
    uint32_t a;
    asm("{ .reg .u64 t; cvta.to.shared.u64 t, %1; cvt.u32.u64 %0, t; }" : "=r"(a) : "l"(p));
    return a;
}

__device__ __forceinline__ uint32_t cvt2bf(float hi, float lo) {
    uint32_t r;
    asm("cvt.rn.bf16x2.f32 %0, %1, %2;" : "=r"(r) : "f"(hi), "f"(lo));
    return r;   // low 16 bits = bf16(lo), high = bf16(hi)
}

__device__ __forceinline__ void cpa16(void* dst, const void* src) {
    unsigned d = (unsigned)__cvta_generic_to_shared(dst);
    asm volatile("cp.async.cg.shared.global [%0], [%1], 16;" :: "r"(d), "l"(src));
}

__device__ __forceinline__ void ldsm4(uint32_t& r0, uint32_t& r1, uint32_t& r2,
                                      uint32_t& r3, uint32_t addr) {
    asm volatile("ldmatrix.sync.aligned.m8n8.x4.shared.b16 {%0,%1,%2,%3}, [%4];"
                 : "=r"(r0), "=r"(r1), "=r"(r2), "=r"(r3) : "r"(addr));
}

__device__ __forceinline__ void mma16816(float* c, const uint32_t* a,
                                         uint32_t b0, uint32_t b1) {
    asm volatile(
        "mma.sync.aligned.m16n8k16.row.col.f32.bf16.bf16.f32 "
        "{%0,%1,%2,%3}, {%4,%5,%6,%7}, {%8,%9}, {%0,%1,%2,%3};"
        : "+f"(c[0]), "+f"(c[1]), "+f"(c[2]), "+f"(c[3])
        : "r"(a[0]), "r"(a[1]), "r"(a[2]), "r"(a[3]), "r"(b0), "r"(b1));
}

// ---------------- prepass ----------------
// one block per (sb, 64-key group). 256 threads.
// V: source already [ch][key] -> direct h/l stores. K: smem transpose.
__global__ __launch_bounds__(256)
void prepass(const float* __restrict__ gK, const float* __restrict__ gV)
{
    __shared__ __nv_bfloat16 T[2][64][KP];   // K staging, 18432 B

    const int bx = blockIdx.x;
    const int grp = bx & 15, sb = bx >> 4;
    const int hwb = grp * 64;
    const int tid = threadIdx.x;

    const float* kb = gK + (size_t)sb * CKD * HWN + hwb;
    const float* vb = gV + (size_t)sb * CKD * HWN + hwb;

    // --- V direct: [ch][key] h/l, 2 keys per op ---
    {
        char* dv = g_VT + (size_t)bx * TILEB;
#pragma unroll
        for (int i = 0; i < 8; i++) {
            int idx = tid + i * 256;                  // 2048 float2 elems
            int c = idx >> 5, k2 = (idx & 31) * 2;
            float2 f = *(const float2*)(vb + (size_t)c * HWN + k2);
            uint32_t h = cvt2bf(f.y, f.x);
            float e0 = f.x - __uint_as_float(h << 16);
            float e1 = f.y - __uint_as_float(h & 0xFFFF0000u);
            uint32_t l = cvt2bf(e1, e0);
            *(uint32_t*)(dv + (size_t)c * ROWB + k2 * 2)          = h;
            *(uint32_t*)(dv + SPLITB + (size_t)c * ROWB + k2 * 2) = l;
        }
    }

    // --- K: transpose to [key][ch] via smem ---
#pragma unroll
    for (int i = 0; i < 16; i++) {
        int idx = tid + i * 256;                      // 4096 elems
        int c = idx >> 6, k = idx & 63;
        float f = kb[(size_t)c * HWN + k];
        __nv_bfloat16 h = __float2bfloat16(f);
        T[0][k][c] = h;
        T[1][k][c] = __float2bfloat16(f - __bfloat162float(h));
    }
    __syncthreads();
    {
        const uint4* src = (const uint4*)&T[0][0][0];
        uint4* dst = (uint4*)(g_KT + (size_t)bx * TILEB);
        for (int idx = tid; idx < 1152; idx += 256) dst[idx] = src[idx];
    }
}

// ---------------- main ----------------
// smem: [0,128) keep bitmask; [128, 128+55296) K tiles [3buf][2split][64][72];
//       [55424, 110720) V tiles same. 1 sync per chunk (3-buf, prefetch-after-compute).
#define KOFF 128
#define VOFF 55424
#define SM_BYTES 110720

__global__ __launch_bounds__(256, 2)
void cfa_main(const float* __restrict__ gQ, const float* __restrict__ gD,
              const int* __restrict__ gS)
{
    extern __shared__ char raw[];
    uint32_t* KeepS = (uint32_t*)raw;
    char* Kraw = raw + KOFF;
    char* Vraw = raw + VOFF;
    const uint32_t sb32 = smem_u32(raw);
    const uint32_t KSB = sb32 + KOFF;
    const uint32_t VSB = sb32 + VOFF;

    const int qt = blockIdx.x, b = blockIdx.y, s = blockIdx.z;
    const int sb = s * NB + b;
    const int tid = threadIdx.x;
    const int w = tid >> 5, lane = tid & 31;
    const int g = lane >> 2, t = lane & 3;
    const int hw0 = qt * 128;

    // prologue: chunks 0 and 1 -> slots 0,1 (two cp.async groups)
#pragma unroll
    for (int cc = 0; cc < 2; cc++) {
        const char* sk = g_KT + (size_t)(sb * NGRP + cc) * TILEB;
        const char* sv = g_VT + (size_t)(sb * NGRP + cc) * TILEB;
#pragma unroll
        for (int j = 0; j < 9; j++) {
            int idx = tid + j * 256;
            if (idx < 1152) cpa16(Kraw + cc * TILEB + idx * 16, sk + idx * 16);
            else            cpa16(Vraw + cc * TILEB + (idx - 1152) * 16,
                                  sv + (idx - 1152) * 16);
        }
        asm volatile("cp.async.commit_group;");
    }

    // keep bitmask: 1024 keys -> 32 words via ballot
    {
        float ddx = (float)gS[(b * SAI + s) * 2 + 0] - 5.f;
        float ddy = (float)gS[(b * SAI + s) * 2 + 1] - 5.f;
        float dist = sqrtf(ddx * ddx + ddy * ddy);
#pragma unroll
        for (int r = 0; r < 4; r++) {
            int key = r * 256 + tid;
            unsigned bit = fabsf(dist * gD[b * HWN + key]) > 0.5f ? 1u : 0u;
            unsigned word = __ballot_sync(0xffffffffu, bit);
            if (lane == 0) KeepS[r * 8 + w] = word;
        }
    }

    // Q fragments (hi/lo), direct from gmem: warp w owns queries [16w,16w+16)
    uint32_t Qh[4][4], Ql[4][4];
    {
        const float* qp = gQ + (size_t)b * CKD * HWN + hw0;
        const int qa = 16 * w + g;
#pragma unroll
        for (int kk = 0; kk < 4; kk++) {
#pragma unroll
            for (int r = 0; r < 4; r++) {
                int rr = qa + ((r & 1) << 3);
                int cc = kk * 16 + 2 * t + ((r & 2) << 2);
                float f0 = qp[(size_t)cc * HWN + rr];
                float f1 = qp[(size_t)(cc + 1) * HWN + rr];
                uint32_t h = cvt2bf(f1, f0);
                float e0 = f0 - __uint_as_float(h << 16);
                float e1 = f1 - __uint_as_float(h & 0xFFFF0000u);
                Qh[kk][r] = h;
                Ql[kk][r] = cvt2bf(e1, e0);
            }
        }
    }

    // ldmatrix per-lane row/col offset (pitch 144B)
    const uint32_t lrow = (uint32_t)((lane & 7) + ((lane >> 4) << 3)) * ROWB
                        + (uint32_t)(((lane >> 3) & 1) << 4);

    float Oacc[8][4];
#pragma unroll
    for (int j = 0; j < 8; j++)
#pragma unroll
        for (int r = 0; r < 4; r++) Oacc[j][r] = 0.f;
    float lrun0 = 0.f, lrun1 = 0.f;

    int slot = 0;
    for (int gc = 0; gc < NGRP; gc++) {
        asm volatile("cp.async.wait_group 1;");   // chunk gc's group complete
        __syncthreads();                          // visible to all; all done with gc-1

        const uint32_t kbase = KSB + slot * TILEB;
        const uint32_t vbase = VSB + slot * TILEB;

        // ---- S = Qh*Kh + Qh*Kl + Ql*Kh  (16q x 64k per warp) ----
        float Sacc[8][4];
#pragma unroll
        for (int j = 0; j < 8; j++)
#pragma unroll
            for (int r = 0; r < 4; r++) Sacc[j][r] = 0.f;

#pragma unroll
        for (int kk = 0; kk < 4; kk++) {
#pragma unroll
            for (int np = 0; np < 4; np++) {
                uint32_t ah = kbase + np * (16 * ROWB) + kk * 32 + lrow;
                uint32_t h0, h1, h2, h3, l0, l1, l2, l3;
                ldsm4(h0, h1, h2, h3, ah);
                ldsm4(l0, l1, l2, l3, ah + SPLITB);
                mma16816(Sacc[2 * np],     Qh[kk], h0, h1);
                mma16816(Sacc[2 * np],     Qh[kk], l0, l1);
                mma16816(Sacc[2 * np],     Ql[kk], h0, h1);
                mma16816(Sacc[2 * np + 1], Qh[kk], h2, h3);
                mma16816(Sacc[2 * np + 1], Qh[kk], l2, l3);
                mma16816(Sacc[2 * np + 1], Ql[kk], h2, h3);
            }
        }

        // ---- P = keep ? exp(S) : 0 ; bf16 h/l fragments ----
        const unsigned w0 = KeepS[2 * gc], w1 = KeepS[2 * gc + 1];
        uint32_t PhA[8], PhB[8], PlA[8], PlB[8];
#pragma unroll
        for (int j = 0; j < 8; j++) {
            unsigned sel = (j < 4) ? w0 : w1;
            int sh = ((8 * j) & 31) + 2 * t;
            bool kp0 = (sel >> sh) & 1;
            bool kp1 = (sel >> (sh + 1)) & 1;
            float p0 = kp0 ? __expf(Sacc[j][0]) : 0.f;
            float p1 = kp1 ? __expf(Sacc[j][1]) : 0.f;
            float p2 = kp0 ? __expf(Sacc[j][2]) : 0.f;
            float p3 = kp1 ? __expf(Sacc[j][3]) : 0.f;
            lrun0 += p0 + p1;
            lrun1 += p2 + p3;
            uint32_t hA = cvt2bf(p1, p0);
            uint32_t hB = cvt2bf(p3, p2);
            PhA[j] = hA; PhB[j] = hB;
            PlA[j] = cvt2bf(p1 - __uint_as_float(hA & 0xFFFF0000u),
                            p0 - __uint_as_float(hA << 16));
            PlB[j] = cvt2bf(p3 - __uint_as_float(hB & 0xFFFF0000u),
                            p2 - __uint_as_float(hB << 16));
        }

        // ---- O += Ph*Vh + Ph*Vl + Pl*Vh  (16q x 64c per warp) ----
#pragma unroll
        for (int kk = 0; kk < 4; kk++) {
            uint32_t ah[4] = {PhA[2 * kk], PhB[2 * kk], PhA[2 * kk + 1], PhB[2 * kk + 1]};
            uint32_t al[4] = {PlA[2 * kk], PlB[2 * kk], PlA[2 * kk + 1], PlB[2 * kk + 1]};
#pragma unroll
            for (int np = 0; np < 4; np++) {
                uint32_t av = vbase + np * (16 * ROWB) + kk * 32 + lrow;
                uint32_t h0, h1, h2, h3, l0, l1, l2, l3;
                ldsm4(h0, h1, h2, h3, av);
                ldsm4(l0, l1, l2, l3, av + SPLITB);
                mma16816(Oacc[2 * np],     ah, h0, h1);
                mma16816(Oacc[2 * np],     ah, l0, l1);
                mma16816(Oacc[2 * np],     al, h0, h1);
                mma16816(Oacc[2 * np + 1], ah, h2, h3);
                mma16816(Oacc[2 * np + 1], ah, l2, l3);
                mma16816(Oacc[2 * np + 1], al, h2, h3);
            }
        }

        // ---- prefetch chunk gc+2 into slot (gc+2)%3 (WAR-safe: after sync+compute) ----
        if (gc + 2 < NGRP) {
            int pslot = slot;          // (gc+2)%3 == (gc-1)%3 == slot before advance? no:
            pslot = slot + 2; if (pslot >= 3) pslot -= 3;
            const char* sk = g_KT + (size_t)(sb * NGRP + gc + 2) * TILEB;
            const char* sv = g_VT + (size_t)(sb * NGRP + gc + 2) * TILEB;
#pragma unroll
            for (int j = 0; j < 9; j++) {
                int idx = tid + j * 256;
                if (idx < 1152) cpa16(Kraw + pslot * TILEB + idx * 16, sk + idx * 16);
                else cpa16(Vraw + pslot * TILEB + (idx - 1152) * 16, sv + (idx - 1152) * 16);
            }
        }
        asm volatile("cp.async.commit_group;");   // (empty group near the tail is fine)

        if (++slot == 3) slot = 0;
    }

    asm volatile("cp.async.wait_group 0;");

    // ---- epilogue ----
    lrun0 += __shfl_xor_sync(0xffffffffu, lrun0, 1);
    lrun0 += __shfl_xor_sync(0xffffffffu, lrun0, 2);
    lrun1 += __shfl_xor_sync(0xffffffffu, lrun1, 1);
    lrun1 += __shfl_xor_sync(0xffffffffu, lrun1, 2);
    const size_t lb = (size_t)(sb * NQT + qt) * 128;
    if (t == 0) {
        g_L[lb + 16 * w + g]     = lrun0;
        g_L[lb + 16 * w + 8 + g] = lrun1;
    }

    float* on = g_On + (size_t)(sb * NQT + qt) * 8192;   // [c][128 q]
    const int qa = 16 * w + g;
#pragma unroll
    for (int j = 0; j < 8; j++) {
        int c = 8 * j + 2 * t;
        on[(size_t)c * 128 + qa]           = Oacc[j][0];
        on[(size_t)(c + 1) * 128 + qa]     = Oacc[j][1];
        on[(size_t)c * 128 + qa + 8]       = Oacc[j][2];
        on[(size_t)(c + 1) * 128 + qa + 8] = Oacc[j][3];
    }
}

// ---------------- reduce (float4) ----------------
__global__ __launch_bounds__(256)
void reduce_k(float* __restrict__ gO)
{
    int i4 = blockIdx.x * 256 + threadIdx.x;    // 65536 float4s
    int b = i4 >> 14;
    int rem = i4 & 16383;
    int c = rem >> 8;
    int q4 = (rem & 255) * 4;                   // hw position
    int qt = q4 >> 7, q = q4 & 127;

    float4 num = make_float4(0.f, 0.f, 0.f, 0.f);
    float4 den = make_float4(0.f, 0.f, 0.f, 0.f);
#pragma unroll
    for (int s = 0; s < SAI; s++) {
        int base = (s * NB + b) * NQT + qt;
        float4 n = *(const float4*)&g_On[(size_t)base * 8192 + c * 128 + q];
        float4 d = *(const float4*)&g_L[(size_t)base * 128 + q];
        num.x += n.x; num.y += n.y; num.z += n.z; num.w += n.w;
        den.x += d.x; den.y += d.y; den.z += d.z; den.w += d.w;
    }
    float4 o = make_float4(num.x / den.x, num.y / den.y, num.z / den.z, num.w / den.w);
    *(float4*)&gO[(size_t)i4 * 4] = o;
}

extern "C" void kernel_launch(void* const* d_in, const int* in_sizes, int n_in,
                              void* d_out, int out_size)
{
    const float* gK = (const float*)d_in[0];  // memory_keys   (9,4,64,32,32)
    const float* gV = (const float*)d_in[1];  // memory_values (9,4,64,32,32)
    const float* gQ = (const float*)d_in[2];  // query_query   (4,64,32,32)
    const float* gD = (const float*)d_in[3];  // disparity     (4,1,32,32)
    const int*   gS = (const int*)d_in[4];    // sequence_index(4,9,2)
    float* gO = (float*)d_out;                // (4,64,32,32)

    cudaFuncSetAttribute(cfa_main, cudaFuncAttributeMaxDynamicSharedMemorySize, SM_BYTES);

    prepass<<<SAI * NB * NGRP, 256>>>(gK, gV);
    dim3 gr(NQT, NB, SAI);
    cfa_main<<<gr, 256, SM_BYTES>>>(gQ, gD, gS);
    reduce_k<<<(NB * 64 * HWN) / 4 / 256, 256>>>(gO);
}

// round 12
// speedup vs baseline: 4.0375x; 1.0030x over previous
#include <cuda_runtime.h>
#include <cuda_bf16.h>
#include <cstdint>
#include <math.h>

// CrossFrameAttention via mma.sync (tcgen05 feature-gated off under compute_103).
//   QK: bf16 hi/lo 3-term split (score abs-err ~2e-4)
//   softmax: per-warp online max (warp owns 16 queries), frames merged via
//            log-sum-exp in reduce (split-k over frames)
//   AV: fp16 P x fp16 V, single term (err ~4e-4, budget 1e-3)

#define SAI 9
#define NB 4
#define CKD 64
#define HWN 1024
#define NGRP 16
#define NQT 8

#define ROWB 144            // row pitch bytes (72 elems x 2B)
#define SPLITB 9216         // one split of K tile [64][72] bf16
#define KTILEB 18432        // K tile: [2 split][64][72] bf16
#define VTILEB 9216         // V tile: [64ch][72key] fp16 (single)

__device__ __align__(16) char g_KT[SAI * NB * NGRP * KTILEB];  // 10.6 MB
__device__ __align__(16) char g_VT[SAI * NB * NGRP * VTILEB];  // 5.3 MB
__device__ float g_On[SAI * NB * NQT * 64 * 128];              // 9.4 MB
__device__ float g_L [SAI * NB * NQT * 128];
__device__ float g_M [SAI * NB * NQT * 128];

// ---------------- helpers ----------------
__device__ __forceinline__ uint32_t smem_u32(const void* p) {
    uint32_t a;
    asm("{ .reg .u64 t; cvta.to.shared.u64 t, %1; cvt.u32.u64 %0, t; }" : "=r"(a) : "l"(p));
    return a;
}

__device__ __forceinline__ uint32_t cvt2bf(float hi, float lo) {
    uint32_t r;
    asm("cvt.rn.bf16x2.f32 %0, %1, %2;" : "=r"(r) : "f"(hi), "f"(lo));
    return r;
}

__device__ __forceinline__ uint32_t cvt2h(float hi, float lo) {
    uint32_t r;
    asm("cvt.rn.f16x2.f32 %0, %1, %2;" : "=r"(r) : "f"(hi), "f"(lo));
    return r;
}

__device__ __forceinline__ void cpa16(void* dst, const void* src) {
    unsigned d = (unsigned)__cvta_generic_to_shared(dst);
    asm volatile("cp.async.cg.shared.global [%0], [%1], 16;" :: "r"(d), "l"(src));
}

__device__ __forceinline__ void ldsm4(uint32_t& r0, uint32_t& r1, uint32_t& r2,
                                      uint32_t& r3, uint32_t addr) {
    asm volatile("ldmatrix.sync.aligned.m8n8.x4.shared.b16 {%0,%1,%2,%3}, [%4];"
                 : "=r"(r0), "=r"(r1), "=r"(r2), "=r"(r3) : "r"(addr));
}

__device__ __forceinline__ void mma_bf16(float* c, const uint32_t* a,
                                         uint32_t b0, uint32_t b1) {
    asm volatile(
        "mma.sync.aligned.m16n8k16.row.col.f32.bf16.bf16.f32 "
        "{%0,%1,%2,%3}, {%4,%5,%6,%7}, {%8,%9}, {%0,%1,%2,%3};"
        : "+f"(c[0]), "+f"(c[1]), "+f"(c[2]), "+f"(c[3])
        : "r"(a[0]), "r"(a[1]), "r"(a[2]), "r"(a[3]), "r"(b0), "r"(b1));
}

__device__ __forceinline__ void mma_f16(float* c, const uint32_t* a,
                                        uint32_t b0, uint32_t b1) {
    asm volatile(
        "mma.sync.aligned.m16n8k16.row.col.f32.f16.f16.f32 "
        "{%0,%1,%2,%3}, {%4,%5,%6,%7}, {%8,%9}, {%0,%1,%2,%3};"
        : "+f"(c[0]), "+f"(c[1]), "+f"(c[2]), "+f"(c[3])
        : "r"(a[0]), "r"(a[1]), "r"(a[2]), "r"(a[3]), "r"(b0), "r"(b1));
}

// ---------------- prepass ----------------
// one block per (sb, 64-key group). K -> bf16 h/l [key][ch] (smem transpose);
// V -> fp16 [ch][key], written directly.
__global__ __launch_bounds__(256)
void prepass(const float* __restrict__ gK, const float* __restrict__ gV)
{
    __shared__ __nv_bfloat16 T[2][64][72];   // K staging

    const int bx = blockIdx.x;
    const int grp = bx & 15, sb = bx >> 4;
    const int hwb = grp * 64;
    const int tid = threadIdx.x;

    const float* kb = gK + (size_t)sb * CKD * HWN + hwb;
    const float* vb = gV + (size_t)sb * CKD * HWN + hwb;

    // --- V direct: fp16 [ch][key], float4 loads (4 keys/op) ---
    {
        char* dv = g_VT + (size_t)bx * VTILEB;
#pragma unroll
        for (int i = 0; i < 4; i++) {
            int idx = tid + i * 256;                  // 1024 float4 ops
            int c = idx >> 4, k4 = (idx & 15) * 4;
            float4 f = *(const float4*)(vb + (size_t)c * HWN + k4);
            uint2 h = make_uint2(cvt2h(f.y, f.x), cvt2h(f.w, f.z));
            *(uint2*)(dv + (size_t)c * ROWB + k4 * 2) = h;
        }
    }

    // --- K: transpose to [key][ch] h/l via smem ---
#pragma unroll
    for (int i = 0; i < 16; i++) {
        int idx = tid + i * 256;                      // 4096 elems
        int c = idx >> 6, k = idx & 63;
        float f = kb[(size_t)c * HWN + k];
        __nv_bfloat16 h = __float2bfloat16(f);
        T[0][k][c] = h;
        T[1][k][c] = __float2bfloat16(f - __bfloat162float(h));
    }
    __syncthreads();
    {
        const uint4* src = (const uint4*)&T[0][0][0];
        uint4* dst = (uint4*)(g_KT + (size_t)bx * KTILEB);
        for (int idx = tid; idx < 1152; idx += 256) dst[idx] = src[idx];
    }
}

// ---------------- main ----------------
// smem: [0,128) keep bitmask; [128, 128+55296) K [3buf][2split][64][72] bf16;
//       [55424, 83072) V [3buf][64][72] fp16.
#define KOFF 128
#define VOFF 55424
#define SM_BYTES 83072

__global__ __launch_bounds__(256, 2)
void cfa_main(const float* __restrict__ gQ, const float* __restrict__ gD,
              const int* __restrict__ gS)
{
    extern __shared__ char raw[];
    uint32_t* KeepS = (uint32_t*)raw;
    char* Kraw = raw + KOFF;
    char* Vraw = raw + VOFF;
    const uint32_t sb32 = smem_u32(raw);
    const uint32_t KSB = sb32 + KOFF;
    const uint32_t VSB = sb32 + VOFF;

    const int qt = blockIdx.x, b = blockIdx.y, s = blockIdx.z;
    const int sb = s * NB + b;
    const int tid = threadIdx.x;
    const int w = tid >> 5, lane = tid & 31;
    const int g = lane >> 2, t = lane & 3;
    const int hw0 = qt * 128;

    // prologue: chunks 0,1 -> slots 0,1
#pragma unroll
    for (int cc = 0; cc < 2; cc++) {
        const char* sk = g_KT + (size_t)(sb * NGRP + cc) * KTILEB;
        const char* sv = g_VT + (size_t)(sb * NGRP + cc) * VTILEB;
#pragma unroll
        for (int j = 0; j < 7; j++) {
            int idx = tid + j * 256;
            if (idx < 1152)       cpa16(Kraw + cc * KTILEB + idx * 16, sk + idx * 16);
            else if (idx < 1728)  cpa16(Vraw + cc * VTILEB + (idx - 1152) * 16,
                                        sv + (idx - 1152) * 16);
        }
        asm volatile("cp.async.commit_group;");
    }

    // keep bitmask: 1024 keys -> 32 words
    {
        float ddx = (float)gS[(b * SAI + s) * 2 + 0] - 5.f;
        float ddy = (float)gS[(b * SAI + s) * 2 + 1] - 5.f;
        float dist = sqrtf(ddx * ddx + ddy * ddy);
#pragma unroll
        for (int r = 0; r < 4; r++) {
            unsigned bit = fabsf(dist * gD[b * HWN + r * 256 + tid]) > 0.5f ? 1u : 0u;
            unsigned word = __ballot_sync(0xffffffffu, bit);
            if (lane == 0) KeepS[r * 8 + w] = word;
        }
    }

    // Q fragments (bf16 hi/lo), warp w owns queries [16w,16w+16)
    uint32_t Qh[4][4], Ql[4][4];
    {
        const float* qp = gQ + (size_t)b * CKD * HWN + hw0;
        const int qa = 16 * w + g;
#pragma unroll
        for (int kk = 0; kk < 4; kk++) {
#pragma unroll
            for (int r = 0; r < 4; r++) {
                int rr = qa + ((r & 1) << 3);
                int cc = kk * 16 + 2 * t + ((r & 2) << 2);
                float f0 = qp[(size_t)cc * HWN + rr];
                float f1 = qp[(size_t)(cc + 1) * HWN + rr];
                uint32_t h = cvt2bf(f1, f0);
                float e0 = f0 - __uint_as_float(h << 16);
                float e1 = f1 - __uint_as_float(h & 0xFFFF0000u);
                Qh[kk][r] = h;
                Ql[kk][r] = cvt2bf(e1, e0);
            }
        }
    }

    const uint32_t lrow = (uint32_t)((lane & 7) + ((lane >> 4) << 3)) * ROWB
                        + (uint32_t)(((lane >> 3) & 1) << 4);

    float Oacc[8][4];
#pragma unroll
    for (int j = 0; j < 8; j++)
#pragma unroll
        for (int r = 0; r < 4; r++) Oacc[j][r] = 0.f;
    float lrun0 = 0.f, lrun1 = 0.f;
    float m0 = -1e4f, m1 = -1e4f;     // per-warp online max (rows qa, qa+8)

    int slot = 0;
    for (int gc = 0; gc < NGRP; gc++) {
        asm volatile("cp.async.wait_group 1;");
        __syncthreads();

        const uint32_t kbase = KSB + slot * KTILEB;
        const uint32_t vbase = VSB + slot * VTILEB;

        // ---- S = Qh*Kh + Qh*Kl + Ql*Kh ----
        float Sacc[8][4];
#pragma unroll
        for (int j = 0; j < 8; j++)
#pragma unroll
            for (int r = 0; r < 4; r++) Sacc[j][r] = 0.f;

#pragma unroll
        for (int kk = 0; kk < 4; kk++) {
#pragma unroll
            for (int np = 0; np < 4; np++) {
                uint32_t ah = kbase + np * (16 * ROWB) + kk * 32 + lrow;
                uint32_t h0, h1, h2, h3, l0, l1, l2, l3;
                ldsm4(h0, h1, h2, h3, ah);
                ldsm4(l0, l1, l2, l3, ah + SPLITB);
                mma_bf16(Sacc[2 * np],     Qh[kk], h0, h1);
                mma_bf16(Sacc[2 * np],     Qh[kk], l0, l1);
                mma_bf16(Sacc[2 * np],     Ql[kk], h0, h1);
                mma_bf16(Sacc[2 * np + 1], Qh[kk], h2, h3);
                mma_bf16(Sacc[2 * np + 1], Qh[kk], l2, l3);
                mma_bf16(Sacc[2 * np + 1], Ql[kk], h2, h3);
            }
        }

        // ---- masked per-warp online max ----
        const unsigned w0 = KeepS[2 * gc], w1 = KeepS[2 * gc + 1];
        float r0mx = -1e30f, r1mx = -1e30f;
        bool kp0a[8], kp1a[8];
#pragma unroll
        for (int j = 0; j < 8; j++) {
            unsigned sel = (j < 4) ? w0 : w1;
            int sh = ((8 * j) & 31) + 2 * t;
            bool kp0 = (sel >> sh) & 1;
            bool kp1 = (sel >> (sh + 1)) & 1;
            kp0a[j] = kp0; kp1a[j] = kp1;
            r0mx = fmaxf(r0mx, fmaxf(kp0 ? Sacc[j][0] : -1e30f,
                                     kp1 ? Sacc[j][1] : -1e30f));
            r1mx = fmaxf(r1mx, fmaxf(kp0 ? Sacc[j][2] : -1e30f,
                                     kp1 ? Sacc[j][3] : -1e30f));
        }
        r0mx = fmaxf(r0mx, __shfl_xor_sync(0xffffffffu, r0mx, 1));
        r0mx = fmaxf(r0mx, __shfl_xor_sync(0xffffffffu, r0mx, 2));
        r1mx = fmaxf(r1mx, __shfl_xor_sync(0xffffffffu, r1mx, 1));
        r1mx = fmaxf(r1mx, __shfl_xor_sync(0xffffffffu, r1mx, 2));

        float m0n = fmaxf(m0, r0mx), m1n = fmaxf(m1, r1mx);
        float sc0 = __expf(m0 - m0n), sc1 = __expf(m1 - m1n);
        m0 = m0n; m1 = m1n;
#pragma unroll
        for (int j = 0; j < 8; j++) {
            Oacc[j][0] *= sc0; Oacc[j][1] *= sc0;
            Oacc[j][2] *= sc1; Oacc[j][3] *= sc1;
        }
        lrun0 *= sc0; lrun1 *= sc1;

        // ---- P = keep ? exp(s - m) : 0 ; fp16 fragments ----
        uint32_t PhA[8], PhB[8];
#pragma unroll
        for (int j = 0; j < 8; j++) {
            float p0 = kp0a[j] ? __expf(Sacc[j][0] - m0) : 0.f;
            float p1 = kp1a[j] ? __expf(Sacc[j][1] - m0) : 0.f;
            float p2 = kp0a[j] ? __expf(Sacc[j][2] - m1) : 0.f;
            float p3 = kp1a[j] ? __expf(Sacc[j][3] - m1) : 0.f;
            lrun0 += p0 + p1;
            lrun1 += p2 + p3;
            PhA[j] = cvt2h(p1, p0);
            PhB[j] = cvt2h(p3, p2);
        }

        // ---- O += P * V (fp16 single term) ----
#pragma unroll
        for (int kk = 0; kk < 4; kk++) {
            uint32_t a[4] = {PhA[2 * kk], PhB[2 * kk], PhA[2 * kk + 1], PhB[2 * kk + 1]};
#pragma unroll
            for (int np = 0; np < 4; np++) {
                uint32_t av = vbase + np * (16 * ROWB) + kk * 32 + lrow;
                uint32_t v0, v1, v2, v3;
                ldsm4(v0, v1, v2, v3, av);
                mma_f16(Oacc[2 * np],     a, v0, v1);
                mma_f16(Oacc[2 * np + 1], a, v2, v3);
            }
        }

        // ---- prefetch chunk gc+2 into slot (gc+2)%3 ----
        if (gc + 2 < NGRP) {
            int pslot = slot + 2; if (pslot >= 3) pslot -= 3;
            const char* sk = g_KT + (size_t)(sb * NGRP + gc + 2) * KTILEB;
            const char* sv = g_VT + (size_t)(sb * NGRP + gc + 2) * VTILEB;
#pragma unroll
            for (int j = 0; j < 7; j++) {
                int idx = tid + j * 256;
                if (idx < 1152)      cpa16(Kraw + pslot * KTILEB + idx * 16, sk + idx * 16);
                else if (idx < 1728) cpa16(Vraw + pslot * VTILEB + (idx - 1152) * 16,
                                           sv + (idx - 1152) * 16);
            }
        }
        asm volatile("cp.async.commit_group;");

        if (++slot == 3) slot = 0;
    }

    asm volatile("cp.async.wait_group 0;");

    // ---- epilogue ----
    lrun0 += __shfl_xor_sync(0xffffffffu, lrun0, 1);
    lrun0 += __shfl_xor_sync(0xffffffffu, lrun0, 2);
    lrun1 += __shfl_xor_sync(0xffffffffu, lrun1, 1);
    lrun1 += __shfl_xor_sync(0xffffffffu, lrun1, 2);
    const size_t lb = (size_t)(sb * NQT + qt) * 128;
    if (t == 0) {
        g_L[lb + 16 * w + g]     = lrun0;
        g_L[lb + 16 * w + 8 + g] = lrun1;
        g_M[lb + 16 * w + g]     = m0;
        g_M[lb + 16 * w + 8 + g] = m1;
    }

    float* on = g_On + (size_t)(sb * NQT + qt) * 8192;   // [c][128 q]
    const int qa = 16 * w + g;
#pragma unroll
    for (int j = 0; j < 8; j++) {
        int c = 8 * j + 2 * t;
        on[(size_t)c * 128 + qa]           = Oacc[j][0];
        on[(size_t)(c + 1) * 128 + qa]     = Oacc[j][1];
        on[(size_t)c * 128 + qa + 8]       = Oacc[j][2];
        on[(size_t)(c + 1) * 128 + qa + 8] = Oacc[j][3];
    }
}

// ---------------- reduce: log-sum-exp merge over frames ----------------
__global__ __launch_bounds__(512)
void reduce_k(float* __restrict__ gO)
{
    const int blk = blockIdx.x;              // b*8 + qt
    const int b = blk >> 3, qt = blk & 7;
    const int q = threadIdx.x & 127, cq = threadIdx.x >> 7;

    float m[SAI], wgt[SAI];
    float M = -1e30f;
#pragma unroll
    for (int f = 0; f < SAI; f++) {
        m[f] = g_M[((size_t)(f * NB + b) * NQT + qt) * 128 + q];
        M = fmaxf(M, m[f]);
    }
    float den = 0.f;
#pragma unroll
    for (int f = 0; f < SAI; f++) {
        wgt[f] = __expf(m[f] - M);
        den += g_L[((size_t)(f * NB + b) * NQT + qt) * 128 + q] * wgt[f];
    }
    float dinv = 1.f / den;

#pragma unroll 4
    for (int ci = 0; ci < 16; ci++) {
        int c = cq * 16 + ci;
        float acc = 0.f;
#pragma unroll
        for (int f = 0; f < SAI; f++)
            acc += g_On[(size_t)((f * NB + b) * NQT + qt) * 8192 + c * 128 + q] * wgt[f];
        gO[((size_t)b * 64 + c) * HWN + qt * 128 + q] = acc * dinv;
    }
}

extern "C" void kernel_launch(void* const* d_in, const int* in_sizes, int n_in,
                              void* d_out, int out_size)
{
    const float* gK = (const float*)d_in[0];  // memory_keys   (9,4,64,32,32)
    const float* gV = (const float*)d_in[1];  // memory_values (9,4,64,32,32)
    const float* gQ = (const float*)d_in[2];  // query_query   (4,64,32,32)
    const float* gD = (const float*)d_in[3];  // disparity     (4,1,32,32)
    const int*   gS = (const int*)d_in[4];    // sequence_index(4,9,2)
    float* gO = (float*)d_out;                // (4,64,32,32)

    cudaFuncSetAttribute(cfa_main, cudaFuncAttributeMaxDynamicSharedMemorySize, SM_BYTES);

    prepass<<<SAI * NB * NGRP, 256>>>(gK, gV);
    dim3 gr(NQT, NB, SAI);
    cfa_main<<<gr, 256, SM_BYTES>>>(gQ, gD, gS);
    reduce_k<<<NB * NQT, 512>>>(gO);
}

// round 13
// speedup vs baseline: 4.0967x; 1.0147x over previous
#include <cuda_runtime.h>
#include <cuda_bf16.h>
#include <cstdint>
#include <math.h>

// CrossFrameAttention via mma.sync (tcgen05 feature-gated off under compute_103).
//   QK: bf16 hi/lo 3-term split; Q fragments via ldmatrix from smem (reg relief)
//   softmax: per-warp online max, frames merged via log-sum-exp in reduce
//   AV: fp16 P x fp16 V single term

#define SAI 9
#define NB 4
#define CKD 64
#define HWN 1024
#define NGRP 16
#define NQT 8

#define ROWB 144            // row pitch bytes (72 elems x 2B)
#define SPLITB 9216         // one split [64][72] bf16
#define KTILEB 18432        // K tile: [2 split][64][72]
#define VTILEB 9216         // V tile: [64ch][72key] fp16
#define QTILEB 18432        // one Q split: [128 q][72 ch] bf16

__device__ __align__(16) char g_KT[SAI * NB * NGRP * KTILEB];  // 10.6 MB
__device__ __align__(16) char g_VT[SAI * NB * NGRP * VTILEB];  // 5.3 MB
__device__ float g_On[SAI * NB * NQT * 64 * 128];              // 9.4 MB
__device__ float g_L [SAI * NB * NQT * 128];
__device__ float g_M [SAI * NB * NQT * 128];

// ---------------- helpers ----------------
__device__ __forceinline__ uint32_t smem_u32(const void* p) {
    uint32_t a;
    asm("{ .reg .u64 t; cvta.to.shared.u64 t, %1; cvt.u32.u64 %0, t; }" : "=r"(a) : "l"(p));
    return a;
}

__device__ __forceinline__ uint32_t cvt2bf(float hi, float lo) {
    uint32_t r;
    asm("cvt.rn.bf16x2.f32 %0, %1, %2;" : "=r"(r) : "f"(hi), "f"(lo));
    return r;
}

__device__ __forceinline__ uint32_t cvt2h(float hi, float lo) {
    uint32_t r;
    asm("cvt.rn.f16x2.f32 %0, %1, %2;" : "=r"(r) : "f"(hi), "f"(lo));
    return r;
}

__device__ __forceinline__ void cpa16(void* dst, const void* src) {
    unsigned d = (unsigned)__cvta_generic_to_shared(dst);
    asm volatile("cp.async.cg.shared.global [%0], [%1], 16;" :: "r"(d), "l"(src));
}

__device__ __forceinline__ void ldsm4(uint32_t& r0, uint32_t& r1, uint32_t& r2,
                                      uint32_t& r3, uint32_t addr) {
    asm volatile("ldmatrix.sync.aligned.m8n8.x4.shared.b16 {%0,%1,%2,%3}, [%4];"
                 : "=r"(r0), "=r"(r1), "=r"(r2), "=r"(r3) : "r"(addr));
}

__device__ __forceinline__ void mma_bf16(float* c, const uint32_t* a,
                                         uint32_t b0, uint32_t b1) {
    asm volatile(
        "mma.sync.aligned.m16n8k16.row.col.f32.bf16.bf16.f32 "
        "{%0,%1,%2,%3}, {%4,%5,%6,%7}, {%8,%9}, {%0,%1,%2,%3};"
        : "+f"(c[0]), "+f"(c[1]), "+f"(c[2]), "+f"(c[3])
        : "r"(a[0]), "r"(a[1]), "r"(a[2]), "r"(a[3]), "r"(b0), "r"(b1));
}

__device__ __forceinline__ void mma_f16(float* c, const uint32_t* a,
                                        uint32_t b0, uint32_t b1) {
    asm volatile(
        "mma.sync.aligned.m16n8k16.row.col.f32.f16.f16.f32 "
        "{%0,%1,%2,%3}, {%4,%5,%6,%7}, {%8,%9}, {%0,%1,%2,%3};"
        : "+f"(c[0]), "+f"(c[1]), "+f"(c[2]), "+f"(c[3])
        : "r"(a[0]), "r"(a[1]), "r"(a[2]), "r"(a[3]), "r"(b0), "r"(b1));
}

// ---------------- prepass ----------------
__global__ __launch_bounds__(256)
void prepass(const float* __restrict__ gK, const float* __restrict__ gV)
{
    __shared__ __nv_bfloat16 T[2][64][72];

    const int bx = blockIdx.x;
    const int grp = bx & 15, sb = bx >> 4;
    const int hwb = grp * 64;
    const int tid = threadIdx.x;

    const float* kb = gK + (size_t)sb * CKD * HWN + hwb;
    const float* vb = gV + (size_t)sb * CKD * HWN + hwb;

    // V direct: fp16 [ch][key]
    {
        char* dv = g_VT + (size_t)bx * VTILEB;
#pragma unroll
        for (int i = 0; i < 4; i++) {
            int idx = tid + i * 256;
            int c = idx >> 4, k4 = (idx & 15) * 4;
            float4 f = *(const float4*)(vb + (size_t)c * HWN + k4);
            uint2 h = make_uint2(cvt2h(f.y, f.x), cvt2h(f.w, f.z));
            *(uint2*)(dv + (size_t)c * ROWB + k4 * 2) = h;
        }
    }

    // K: transpose to [key][ch] h/l
#pragma unroll
    for (int i = 0; i < 16; i++) {
        int idx = tid + i * 256;
        int c = idx >> 6, k = idx & 63;
        float f = kb[(size_t)c * HWN + k];
        __nv_bfloat16 h = __float2bfloat16(f);
        T[0][k][c] = h;
        T[1][k][c] = __float2bfloat16(f - __bfloat162float(h));
    }
    __syncthreads();
    {
        const uint4* src = (const uint4*)&T[0][0][0];
        uint4* dst = (uint4*)(g_KT + (size_t)bx * KTILEB);
        for (int idx = tid; idx < 1152; idx += 256) dst[idx] = src[idx];
    }
}

// ---------------- main ----------------
// smem: [0,128) keep bitmask; [128, +36864) Q [2 split][128][72] bf16;
//       [36992, +36864) K [2 slot][2 split][64][72]; [73856, +18432) V [2 slot][64][72] fp16
#define QOFF 128
#define KOFF 36992
#define VOFF 73856
#define SM_BYTES 92288

__global__ __launch_bounds__(256, 2)
void cfa_main(const float* __restrict__ gQ, const float* __restrict__ gD,
              const int* __restrict__ gS)
{
    extern __shared__ char raw[];
    uint32_t* KeepS = (uint32_t*)raw;
    char* Kraw = raw + KOFF;
    char* Vraw = raw + VOFF;
    const uint32_t sb32 = smem_u32(raw);
    const uint32_t QSB = sb32 + QOFF;
    const uint32_t KSB = sb32 + KOFF;
    const uint32_t VSB = sb32 + VOFF;

    const int qt = blockIdx.x, b = blockIdx.y, s = blockIdx.z;
    const int sb = s * NB + b;
    const int tid = threadIdx.x;
    const int w = tid >> 5, lane = tid & 31;
    const int g = lane >> 2, t = lane & 3;
    const int hw0 = qt * 128;

    // prologue: chunk 0 -> slot 0
    {
        const char* sk = g_KT + (size_t)(sb * NGRP) * KTILEB;
        const char* sv = g_VT + (size_t)(sb * NGRP) * VTILEB;
#pragma unroll
        for (int j = 0; j < 7; j++) {
            int idx = tid + j * 256;
            if (idx < 1152)      cpa16(Kraw + idx * 16, sk + idx * 16);
            else if (idx < 1728) cpa16(Vraw + (idx - 1152) * 16, sv + (idx - 1152) * 16);
        }
        asm volatile("cp.async.commit_group;");
    }

    // keep bitmask
    {
        float ddx = (float)gS[(b * SAI + s) * 2 + 0] - 5.f;
        float ddy = (float)gS[(b * SAI + s) * 2 + 1] - 5.f;
        float dist = sqrtf(ddx * ddx + ddy * ddy);
#pragma unroll
        for (int r = 0; r < 4; r++) {
            unsigned bit = fabsf(dist * gD[b * HWN + r * 256 + tid]) > 0.5f ? 1u : 0u;
            unsigned word = __ballot_sync(0xffffffffu, bit);
            if (lane == 0) KeepS[r * 8 + w] = word;
        }
    }

    // Q tile: [q][c] bf16 h/l into smem (one time)
    {
        const float* qp = gQ + (size_t)b * CKD * HWN + hw0;
        __nv_bfloat16* qh = (__nv_bfloat16*)(raw + QOFF);
        __nv_bfloat16* ql = (__nv_bfloat16*)(raw + QOFF + QTILEB);
#pragma unroll
        for (int i = 0; i < 32; i++) {
            int idx = tid + i * 256;                 // 8192 = 64c x 128q
            int c = idx >> 7, q = idx & 127;
            float f = qp[(size_t)c * HWN + q];
            __nv_bfloat16 h = __float2bfloat16(f);
            qh[q * 72 + c] = h;
            ql[q * 72 + c] = __float2bfloat16(f - __bfloat162float(h));
        }
    }

    // ldsm addressing
    // B-fragment (K/V tiles): b0 k0-7/n0-7, b1 k8-15/n0-7, b2 k0-7/n8-15, b3 k8-15/n8-15
    const uint32_t lrow = (uint32_t)((lane & 7) + ((lane >> 4) << 3)) * ROWB
                        + (uint32_t)(((lane >> 3) & 1) << 4);
    // A-fragment (Q tile): a0 r0-7/k0-7, a1 r8-15/k0-7, a2 r0-7/k8-15, a3 r8-15/k8-15
    const uint32_t arow = (uint32_t)((lane & 7) + (((lane >> 3) & 1) << 3)) * ROWB
                        + (uint32_t)((lane >> 4) << 4);
    const uint32_t qbase = QSB + (uint32_t)(16 * w) * ROWB + arow;

    float Oacc[8][4];
#pragma unroll
    for (int j = 0; j < 8; j++)
#pragma unroll
        for (int r = 0; r < 4; r++) Oacc[j][r] = 0.f;
    float lrun0 = 0.f, lrun1 = 0.f;
    float m0 = -1e4f, m1 = -1e4f;

    __syncthreads();   // Q tile + keep mask visible

    for (int gc = 0; gc < NGRP; gc++) {
        const int slot = gc & 1;

        asm volatile("cp.async.wait_group 0;");   // chunk gc resident
        __syncthreads();                          // all warps done reading slot^1 (gc-1)

        // prefetch gc+1 into slot^1
        if (gc + 1 < NGRP) {
            const char* sk = g_KT + (size_t)(sb * NGRP + gc + 1) * KTILEB;
            const char* sv = g_VT + (size_t)(sb * NGRP + gc + 1) * VTILEB;
            const int ps = slot ^ 1;
#pragma unroll
            for (int j = 0; j < 7; j++) {
                int idx = tid + j * 256;
                if (idx < 1152)      cpa16(Kraw + ps * KTILEB + idx * 16, sk + idx * 16);
                else if (idx < 1728) cpa16(Vraw + ps * VTILEB + (idx - 1152) * 16,
                                           sv + (idx - 1152) * 16);
            }
        }
        asm volatile("cp.async.commit_group;");

        const uint32_t kbase = KSB + slot * KTILEB;
        const uint32_t vbase = VSB + slot * VTILEB;

        // ---- S = Qh*Kh + Qh*Kl + Ql*Kh ----
        float Sacc[8][4];
#pragma unroll
        for (int j = 0; j < 8; j++)
#pragma unroll
            for (int r = 0; r < 4; r++) Sacc[j][r] = 0.f;

#pragma unroll
        for (int kk = 0; kk < 4; kk++) {
            uint32_t qh[4], ql[4];
            ldsm4(qh[0], qh[1], qh[2], qh[3], qbase + kk * 32);
            ldsm4(ql[0], ql[1], ql[2], ql[3], qbase + kk * 32 + QTILEB);
#pragma unroll
            for (int np = 0; np < 4; np++) {
                uint32_t ah = kbase + np * (16 * ROWB) + kk * 32 + lrow;
                uint32_t h0, h1, h2, h3, l0, l1, l2, l3;
                ldsm4(h0, h1, h2, h3, ah);
                ldsm4(l0, l1, l2, l3, ah + SPLITB);
                mma_bf16(Sacc[2 * np],     qh, h0, h1);
                mma_bf16(Sacc[2 * np],     qh, l0, l1);
                mma_bf16(Sacc[2 * np],     ql, h0, h1);
                mma_bf16(Sacc[2 * np + 1], qh, h2, h3);
                mma_bf16(Sacc[2 * np + 1], qh, l2, l3);
                mma_bf16(Sacc[2 * np + 1], ql, h2, h3);
            }
        }

        // ---- masked per-warp online max ----
        const unsigned w0 = KeepS[2 * gc], w1 = KeepS[2 * gc + 1];
        float r0mx = -1e30f, r1mx = -1e30f;
        bool kp0a[8], kp1a[8];
#pragma unroll
        for (int j = 0; j < 8; j++) {
            unsigned sel = (j < 4) ? w0 : w1;
            int sh = ((8 * j) & 31) + 2 * t;
            bool kp0 = (sel >> sh) & 1;
            bool kp1 = (sel >> (sh + 1)) & 1;
            kp0a[j] = kp0; kp1a[j] = kp1;
            r0mx = fmaxf(r0mx, fmaxf(kp0 ? Sacc[j][0] : -1e30f,
                                     kp1 ? Sacc[j][1] : -1e30f));
            r1mx = fmaxf(r1mx, fmaxf(kp0 ? Sacc[j][2] : -1e30f,
                                     kp1 ? Sacc[j][3] : -1e30f));
        }
        r0mx = fmaxf(r0mx, __shfl_xor_sync(0xffffffffu, r0mx, 1));
        r0mx = fmaxf(r0mx, __shfl_xor_sync(0xffffffffu, r0mx, 2));
        r1mx = fmaxf(r1mx, __shfl_xor_sync(0xffffffffu, r1mx, 1));
        r1mx = fmaxf(r1mx, __shfl_xor_sync(0xffffffffu, r1mx, 2));

        float m0n = fmaxf(m0, r0mx), m1n = fmaxf(m1, r1mx);
        float sc0 = __expf(m0 - m0n), sc1 = __expf(m1 - m1n);
        m0 = m0n; m1 = m1n;
#pragma unroll
        for (int j = 0; j < 8; j++) {
            Oacc[j][0] *= sc0; Oacc[j][1] *= sc0;
            Oacc[j][2] *= sc1; Oacc[j][3] *= sc1;
        }
        lrun0 *= sc0; lrun1 *= sc1;

        // ---- P = keep ? exp(s - m) : 0 ; fp16 fragments ----
        uint32_t PhA[8], PhB[8];
#pragma unroll
        for (int j = 0; j < 8; j++) {
            float p0 = kp0a[j] ? __expf(Sacc[j][0] - m0) : 0.f;
            float p1 = kp1a[j] ? __expf(Sacc[j][1] - m0) : 0.f;
            float p2 = kp0a[j] ? __expf(Sacc[j][2] - m1) : 0.f;
            float p3 = kp1a[j] ? __expf(Sacc[j][3] - m1) : 0.f;
            lrun0 += p0 + p1;
            lrun1 += p2 + p3;
            PhA[j] = cvt2h(p1, p0);
            PhB[j] = cvt2h(p3, p2);
        }

        // ---- O += P * V ----
#pragma unroll
        for (int kk = 0; kk < 4; kk++) {
            uint32_t a[4] = {PhA[2 * kk], PhB[2 * kk], PhA[2 * kk + 1], PhB[2 * kk + 1]};
#pragma unroll
            for (int np = 0; np < 4; np++) {
                uint32_t av = vbase + np * (16 * ROWB) + kk * 32 + lrow;
                uint32_t v0, v1, v2, v3;
                ldsm4(v0, v1, v2, v3, av);
                mma_f16(Oacc[2 * np],     a, v0, v1);
                mma_f16(Oacc[2 * np + 1], a, v2, v3);
            }
        }
    }

    asm volatile("cp.async.wait_group 0;");

    // ---- epilogue ----
    lrun0 += __shfl_xor_sync(0xffffffffu, lrun0, 1);
    lrun0 += __shfl_xor_sync(0xffffffffu, lrun0, 2);
    lrun1 += __shfl_xor_sync(0xffffffffu, lrun1, 1);
    lrun1 += __shfl_xor_sync(0xffffffffu, lrun1, 2);
    const size_t lb = (size_t)(sb * NQT + qt) * 128;
    if (t == 0) {
        g_L[lb + 16 * w + g]     = lrun0;
        g_L[lb + 16 * w + 8 + g] = lrun1;
        g_M[lb + 16 * w + g]     = m0;
        g_M[lb + 16 * w + 8 + g] = m1;
    }

    float* on = g_On + (size_t)(sb * NQT + qt) * 8192;   // [c][128 q]
    const int qa = 16 * w + g;
#pragma unroll
    for (int j = 0; j < 8; j++) {
        int c = 8 * j + 2 * t;
        on[(size_t)c * 128 + qa]           = Oacc[j][0];
        on[(size_t)(c + 1) * 128 + qa]     = Oacc[j][1];
        on[(size_t)c * 128 + qa + 8]       = Oacc[j][2];
        on[(size_t)(c + 1) * 128 + qa + 8] = Oacc[j][3];
    }
}

// ---------------- reduce: log-sum-exp merge over frames ----------------
__global__ __launch_bounds__(512)
void reduce_k(float* __restrict__ gO)
{
    const int blk = blockIdx.x;              // b*8 + qt
    const int b = blk >> 3, qt = blk & 7;
    const int q = threadIdx.x & 127, cq = threadIdx.x >> 7;

    float m[SAI], wgt[SAI];
    float M = -1e30f;
#pragma unroll
    for (int f = 0; f < SAI; f++) {
        m[f] = g_M[((size_t)(f * NB + b) * NQT + qt) * 128 + q];
        M = fmaxf(M, m[f]);
    }
    float den = 0.f;
#pragma unroll
    for (int f = 0; f < SAI; f++) {
        wgt[f] = __expf(m[f] - M);
        den += g_L[((size_t)(f * NB + b) * NQT + qt) * 128 + q] * wgt[f];
    }
    float dinv = 1.f / den;

#pragma unroll 4
    for (int ci = 0; ci < 16; ci++) {
        int c = cq * 16 + ci;
        float acc = 0.f;
#pragma unroll
        for (int f = 0; f < SAI; f++)
            acc += g_On[(size_t)((f * NB + b) * NQT + qt) * 8192 + c * 128 + q] * wgt[f];
        gO[((size_t)b * 64 + c) * HWN + qt * 128 + q] = acc * dinv;
    }
}

extern "C" void kernel_launch(void* const* d_in, const int* in_sizes, int n_in,
                              void* d_out, int out_size)
{
    const float* gK = (const float*)d_in[0];  // memory_keys   (9,4,64,32,32)
    const float* gV = (const float*)d_in[1];  // memory_values (9,4,64,32,32)
    const float* gQ = (const float*)d_in[2];  // query_query   (4,64,32,32)
    const float* gD = (const float*)d_in[3];  // disparity     (4,1,32,32)
    const int*   gS = (const int*)d_in[4];    // sequence_index(4,9,2)
    float* gO = (float*)d_out;                // (4,64,32,32)

    cudaFuncSetAttribute(cfa_main, cudaFuncAttributeMaxDynamicSharedMemorySize, SM_BYTES);

    prepass<<<SAI * NB * NGRP, 256>>>(gK, gV);
    dim3 gr(NQT, NB, SAI);
    cfa_main<<<gr, 256, SM_BYTES>>>(gQ, gD, gS);
    reduce_k<<<NB * NQT, 512>>>(gO);
}

// round 14
// speedup vs baseline: 4.2141x; 1.0286x over previous
#include <cuda_runtime.h>
#include <cuda_bf16.h>
#include <cstdint>
#include <math.h>

// CrossFrameAttention via mma.sync (tcgen05 feature-gated off under compute_103).
//   QK: bf16 hi/lo 3-term split; fragments via ldmatrix, manually double-buffered
//   softmax: per-warp online max in log2 domain (Q pre-scaled by log2e),
//            frames merged via log-sum-exp in reduce (split-k over frames)
//   AV: fp16 P x fp16 V single term, V fragments double-buffered

#define SAI 9
#define NB 4
#define CKD 64
#define HWN 1024
#define NGRP 16
#define NQT 8

#define ROWB 144            // row pitch bytes (72 elems x 2B)
#define SPLITB 9216         // one split [64][72] bf16
#define KTILEB 18432        // K tile: [2 split][64][72]
#define VTILEB 9216         // V tile: [64ch][72key] fp16
#define QTILEB 18432        // one Q split: [128 q][72 ch] bf16

__device__ __align__(16) char g_KT[SAI * NB * NGRP * KTILEB];  // 10.6 MB
__device__ __align__(16) char g_VT[SAI * NB * NGRP * VTILEB];  // 5.3 MB
__device__ float g_On[SAI * NB * NQT * 64 * 128];              // 9.4 MB
__device__ float g_L [SAI * NB * NQT * 128];
__device__ float g_M [SAI * NB * NQT * 128];

// ---------------- helpers ----------------
__device__ __forceinline__ uint32_t smem_u32(const void* p) {
    uint32_t a;
    asm("{ .reg .u64 t; cvta.to.shared.u64 t, %1; cvt.u32.u64 %0, t; }" : "=r"(a) : "l"(p));
    return a;
}

__device__ __forceinline__ uint32_t cvt2bf(float hi, float lo) {
    uint32_t r;
    asm("cvt.rn.bf16x2.f32 %0, %1, %2;" : "=r"(r) : "f"(hi), "f"(lo));
    return r;
}

__device__ __forceinline__ uint32_t cvt2h(float hi, float lo) {
    uint32_t r;
    asm("cvt.rn.f16x2.f32 %0, %1, %2;" : "=r"(r) : "f"(hi), "f"(lo));
    return r;
}

__device__ __forceinline__ void cpa16(void* dst, const void* src) {
    unsigned d = (unsigned)__cvta_generic_to_shared(dst);
    asm volatile("cp.async.cg.shared.global [%0], [%1], 16;" :: "r"(d), "l"(src));
}

__device__ __forceinline__ void ldsm4(uint32_t* r, uint32_t addr) {
    asm volatile("ldmatrix.sync.aligned.m8n8.x4.shared.b16 {%0,%1,%2,%3}, [%4];"
                 : "=r"(r[0]), "=r"(r[1]), "=r"(r[2]), "=r"(r[3]) : "r"(addr));
}

__device__ __forceinline__ void mma_bf16(float* c, const uint32_t* a,
                                         uint32_t b0, uint32_t b1) {
    asm volatile(
        "mma.sync.aligned.m16n8k16.row.col.f32.bf16.bf16.f32 "
        "{%0,%1,%2,%3}, {%4,%5,%6,%7}, {%8,%9}, {%0,%1,%2,%3};"
        : "+f"(c[0]), "+f"(c[1]), "+f"(c[2]), "+f"(c[3])
        : "r"(a[0]), "r"(a[1]), "r"(a[2]), "r"(a[3]), "r"(b0), "r"(b1));
}

__device__ __forceinline__ void mma_f16(float* c, const uint32_t* a,
                                        uint32_t b0, uint32_t b1) {
    asm volatile(
        "mma.sync.aligned.m16n8k16.row.col.f32.f16.f16.f32 "
        "{%0,%1,%2,%3}, {%4,%5,%6,%7}, {%8,%9}, {%0,%1,%2,%3};"
        : "+f"(c[0]), "+f"(c[1]), "+f"(c[2]), "+f"(c[3])
        : "r"(a[0]), "r"(a[1]), "r"(a[2]), "r"(a[3]), "r"(b0), "r"(b1));
}

// ---------------- prepass ----------------
__global__ __launch_bounds__(256)
void prepass(const float* __restrict__ gK, const float* __restrict__ gV)
{
    __shared__ __nv_bfloat16 T[2][64][72];

    const int bx = blockIdx.x;
    const int grp = bx & 15, sb = bx >> 4;
    const int hwb = grp * 64;
    const int tid = threadIdx.x;

    const float* kb = gK + (size_t)sb * CKD * HWN + hwb;
    const float* vb = gV + (size_t)sb * CKD * HWN + hwb;

    // V direct: fp16 [ch][key]
    {
        char* dv = g_VT + (size_t)bx * VTILEB;
#pragma unroll
        for (int i = 0; i < 4; i++) {
            int idx = tid + i * 256;
            int c = idx >> 4, k4 = (idx & 15) * 4;
            float4 f = *(const float4*)(vb + (size_t)c * HWN + k4);
            uint2 h = make_uint2(cvt2h(f.y, f.x), cvt2h(f.w, f.z));
            *(uint2*)(dv + (size_t)c * ROWB + k4 * 2) = h;
        }
    }

    // K: transpose to [key][ch] h/l
#pragma unroll
    for (int i = 0; i < 16; i++) {
        int idx = tid + i * 256;
        int c = idx >> 6, k = idx & 63;
        float f = kb[(size_t)c * HWN + k];
        __nv_bfloat16 h = __float2bfloat16(f);
        T[0][k][c] = h;
        T[1][k][c] = __float2bfloat16(f - __bfloat162float(h));
    }
    __syncthreads();
    {
        const uint4* src = (const uint4*)&T[0][0][0];
        uint4* dst = (uint4*)(g_KT + (size_t)bx * KTILEB);
        for (int idx = tid; idx < 1152; idx += 256) dst[idx] = src[idx];
    }
}

// ---------------- main ----------------
// smem: [0,128) keep bitmask; [128, +36864) Q [2 split][128][72] bf16;
//       [36992, +36864) K [2 slot][2 split][64][72]; [73856, +18432) V [2 slot][64][72] fp16
#define QOFF 128
#define KOFF 36992
#define VOFF 73856
#define SM_BYTES 92288

__global__ __launch_bounds__(256, 2)
void cfa_main(const float* __restrict__ gQ, const float* __restrict__ gD,
              const int* __restrict__ gS)
{
    extern __shared__ char raw[];
    uint32_t* KeepS = (uint32_t*)raw;
    char* Kraw = raw + KOFF;
    char* Vraw = raw + VOFF;
    const uint32_t sb32 = smem_u32(raw);
    const uint32_t QSB = sb32 + QOFF;
    const uint32_t KSB = sb32 + KOFF;
    const uint32_t VSB = sb32 + VOFF;

    const int qt = blockIdx.x, b = blockIdx.y, s = blockIdx.z;
    const int sb = s * NB + b;
    const int tid = threadIdx.x;
    const int w = tid >> 5, lane = tid & 31;
    const int g = lane >> 2, t = lane & 3;
    const int hw0 = qt * 128;

    // prologue: chunk 0 -> slot 0
    {
        const char* sk = g_KT + (size_t)(sb * NGRP) * KTILEB;
        const char* sv = g_VT + (size_t)(sb * NGRP) * VTILEB;
#pragma unroll
        for (int j = 0; j < 7; j++) {
            int idx = tid + j * 256;
            if (idx < 1152)      cpa16(Kraw + idx * 16, sk + idx * 16);
            else if (idx < 1728) cpa16(Vraw + (idx - 1152) * 16, sv + (idx - 1152) * 16);
        }
        asm volatile("cp.async.commit_group;");
    }

    // keep bitmask
    {
        float ddx = (float)gS[(b * SAI + s) * 2 + 0] - 5.f;
        float ddy = (float)gS[(b * SAI + s) * 2 + 1] - 5.f;
        float dist = sqrtf(ddx * ddx + ddy * ddy);
#pragma unroll
        for (int r = 0; r < 4; r++) {
            unsigned bit = fabsf(dist * gD[b * HWN + r * 256 + tid]) > 0.5f ? 1u : 0u;
            unsigned word = __ballot_sync(0xffffffffu, bit);
            if (lane == 0) KeepS[r * 8 + w] = word;
        }
    }

    // Q tile: [q][c] bf16 h/l into smem, PRE-SCALED by log2(e) (exp -> exp2)
    {
        const float* qp = gQ + (size_t)b * CKD * HWN + hw0;
        __nv_bfloat16* qh = (__nv_bfloat16*)(raw + QOFF);
        __nv_bfloat16* ql = (__nv_bfloat16*)(raw + QOFF + QTILEB);
#pragma unroll
        for (int i = 0; i < 32; i++) {
            int idx = tid + i * 256;                 // 8192 = 64c x 128q
            int c = idx >> 7, q = idx & 127;
            float f = qp[(size_t)c * HWN + q] * 1.4426950408889634f;
            __nv_bfloat16 h = __float2bfloat16(f);
            qh[q * 72 + c] = h;
            ql[q * 72 + c] = __float2bfloat16(f - __bfloat162float(h));
        }
    }

    // ldsm addressing
    const uint32_t lrow = (uint32_t)((lane & 7) + ((lane >> 4) << 3)) * ROWB
                        + (uint32_t)(((lane >> 3) & 1) << 4);
    const uint32_t arow = (uint32_t)((lane & 7) + (((lane >> 3) & 1) << 3)) * ROWB
                        + (uint32_t)((lane >> 4) << 4);
    const uint32_t qbase = QSB + (uint32_t)(16 * w) * ROWB + arow;

    float Oacc[8][4];
#pragma unroll
    for (int j = 0; j < 8; j++)
#pragma unroll
        for (int r = 0; r < 4; r++) Oacc[j][r] = 0.f;
    float lrun0 = 0.f, lrun1 = 0.f;
    float m0 = -1e4f, m1 = -1e4f;        // log2-domain running max

    __syncthreads();   // Q tile + keep mask visible

    for (int gc = 0; gc < NGRP; gc++) {
        const int slot = gc & 1;

        asm volatile("cp.async.wait_group 0;");   // chunk gc resident
        __syncthreads();                          // all warps done reading slot^1

        // prefetch gc+1 into slot^1
        if (gc + 1 < NGRP) {
            const char* sk = g_KT + (size_t)(sb * NGRP + gc + 1) * KTILEB;
            const char* sv = g_VT + (size_t)(sb * NGRP + gc + 1) * VTILEB;
            const int ps = slot ^ 1;
#pragma unroll
            for (int j = 0; j < 7; j++) {
                int idx = tid + j * 256;
                if (idx < 1152)      cpa16(Kraw + ps * KTILEB + idx * 16, sk + idx * 16);
                else if (idx < 1728) cpa16(Vraw + ps * VTILEB + (idx - 1152) * 16,
                                           sv + (idx - 1152) * 16);
            }
        }
        asm volatile("cp.async.commit_group;");

        const uint32_t kbase = KSB + slot * KTILEB;
        const uint32_t vbase = VSB + slot * VTILEB;

        // ---- S = Qh*Kh + Qh*Kl + Ql*Kh (K fragments double-buffered) ----
        float Sacc[8][4];
#pragma unroll
        for (int j = 0; j < 8; j++)
#pragma unroll
            for (int r = 0; r < 4; r++) Sacc[j][r] = 0.f;

#pragma unroll
        for (int kk = 0; kk < 4; kk++) {
            uint32_t qh[4], ql[4];
            ldsm4(qh, qbase + kk * 32);
            ldsm4(ql, qbase + kk * 32 + QTILEB);

            uint32_t kf[2][8];   // [buf][ h0..h3, l0..l3 ]
            ldsm4(&kf[0][0], kbase + kk * 32 + lrow);
            ldsm4(&kf[0][4], kbase + kk * 32 + lrow + SPLITB);
#pragma unroll
            for (int np = 0; np < 4; np++) {
                const int nb = np & 1;
                if (np < 3) {
                    uint32_t ah = kbase + (np + 1) * (16 * ROWB) + kk * 32 + lrow;
                    ldsm4(&kf[nb ^ 1][0], ah);
                    ldsm4(&kf[nb ^ 1][4], ah + SPLITB);
                }
                const uint32_t* f = kf[nb];
                // interleaved acc0/acc1 to halve dependent-MMA chains
                mma_bf16(Sacc[2 * np],     qh, f[0], f[1]);
                mma_bf16(Sacc[2 * np + 1], qh, f[2], f[3]);
                mma_bf16(Sacc[2 * np],     qh, f[4], f[5]);
                mma_bf16(Sacc[2 * np + 1], qh, f[6], f[7]);
                mma_bf16(Sacc[2 * np],     ql, f[0], f[1]);
                mma_bf16(Sacc[2 * np + 1], ql, f[2], f[3]);
            }
        }

        // ---- masked per-warp online max (log2 domain) ----
        const unsigned w0 = KeepS[2 * gc], w1 = KeepS[2 * gc + 1];
        float r0mx = -1e30f, r1mx = -1e30f;
        bool kp0a[8], kp1a[8];
#pragma unroll
        for (int j = 0; j < 8; j++) {
            unsigned sel = (j < 4) ? w0 : w1;
            int sh = ((8 * j) & 31) + 2 * t;
            bool kp0 = (sel >> sh) & 1;
            bool kp1 = (sel >> (sh + 1)) & 1;
            kp0a[j] = kp0; kp1a[j] = kp1;
            r0mx = fmaxf(r0mx, fmaxf(kp0 ? Sacc[j][0] : -1e30f,
                                     kp1 ? Sacc[j][1] : -1e30f));
            r1mx = fmaxf(r1mx, fmaxf(kp0 ? Sacc[j][2] : -1e30f,
                                     kp1 ? Sacc[j][3] : -1e30f));
        }
        r0mx = fmaxf(r0mx, __shfl_xor_sync(0xffffffffu, r0mx, 1));
        r0mx = fmaxf(r0mx, __shfl_xor_sync(0xffffffffu, r0mx, 2));
        r1mx = fmaxf(r1mx, __shfl_xor_sync(0xffffffffu, r1mx, 1));
        r1mx = fmaxf(r1mx, __shfl_xor_sync(0xffffffffu, r1mx, 2));

        float m0n = fmaxf(m0, r0mx), m1n = fmaxf(m1, r1mx);
        float sc0 = exp2f(m0 - m0n), sc1 = exp2f(m1 - m1n);
        m0 = m0n; m1 = m1n;
#pragma unroll
        for (int j = 0; j < 8; j++) {
            Oacc[j][0] *= sc0; Oacc[j][1] *= sc0;
            Oacc[j][2] *= sc1; Oacc[j][3] *= sc1;
        }
        lrun0 *= sc0; lrun1 *= sc1;

        // ---- P = keep ? exp2(s - m) : 0 ; fp16 fragments ----
        uint32_t PhA[8], PhB[8];
#pragma unroll
        for (int j = 0; j < 8; j++) {
            float p0 = kp0a[j] ? exp2f(Sacc[j][0] - m0) : 0.f;
            float p1 = kp1a[j] ? exp2f(Sacc[j][1] - m0) : 0.f;
            float p2 = kp0a[j] ? exp2f(Sacc[j][2] - m1) : 0.f;
            float p3 = kp1a[j] ? exp2f(Sacc[j][3] - m1) : 0.f;
            lrun0 += p0 + p1;
            lrun1 += p2 + p3;
            PhA[j] = cvt2h(p1, p0);
            PhB[j] = cvt2h(p3, p2);
        }

        // ---- O += P * V (V fragments double-buffered over flattened 16 iters) ----
        {
            uint32_t vf[2][4];
            ldsm4(vf[0], vbase + lrow);          // (kk=0, np=0)
#pragma unroll
            for (int it = 0; it < 16; it++) {
                const int kk = it >> 2, np = it & 3;
                const int nb = it & 1;
                if (it < 15) {
                    const int kk2 = (it + 1) >> 2, np2 = (it + 1) & 3;
                    ldsm4(vf[nb ^ 1], vbase + np2 * (16 * ROWB) + kk2 * 32 + lrow);
                }
                uint32_t a[4] = {PhA[2 * kk], PhB[2 * kk], PhA[2 * kk + 1], PhB[2 * kk + 1]};
                mma_f16(Oacc[2 * np + ((kk & 0) )], a, vf[nb][0], vf[nb][1]);   // acc 2np
                mma_f16(Oacc[2 * np + 1],           a, vf[nb][2], vf[nb][3]);   // acc 2np+1
            }
        }
    }

    asm volatile("cp.async.wait_group 0;");

    // ---- epilogue ----
    lrun0 += __shfl_xor_sync(0xffffffffu, lrun0, 1);
    lrun0 += __shfl_xor_sync(0xffffffffu, lrun0, 2);
    lrun1 += __shfl_xor_sync(0xffffffffu, lrun1, 1);
    lrun1 += __shfl_xor_sync(0xffffffffu, lrun1, 2);
    const size_t lb = (size_t)(sb * NQT + qt) * 128;
    if (t == 0) {
        g_L[lb + 16 * w + g]     = lrun0;
        g_L[lb + 16 * w + 8 + g] = lrun1;
        g_M[lb + 16 * w + g]     = m0;
        g_M[lb + 16 * w + 8 + g] = m1;
    }

    float* on = g_On + (size_t)(sb * NQT + qt) * 8192;   // [c][128 q]
    const int qa = 16 * w + g;
#pragma unroll
    for (int j = 0; j < 8; j++) {
        int c = 8 * j + 2 * t;
        on[(size_t)c * 128 + qa]           = Oacc[j][0];
        on[(size_t)(c + 1) * 128 + qa]     = Oacc[j][1];
        on[(size_t)c * 128 + qa + 8]       = Oacc[j][2];
        on[(size_t)(c + 1) * 128 + qa + 8] = Oacc[j][3];
    }
}

// ---------------- reduce: log-sum-exp merge over frames (log2 domain) ----------------
__global__ __launch_bounds__(512)
void reduce_k(float* __restrict__ gO)
{
    const int blk = blockIdx.x;              // b*8 + qt
    const int b = blk >> 3, qt = blk & 7;
    const int q = threadIdx.x & 127, cq = threadIdx.x >> 7;

    float m[SAI], wgt[SAI];
    float M = -1e30f;
#pragma unroll
    for (int f = 0; f < SAI; f++) {
        m[f] = g_M[((size_t)(f * NB + b) * NQT + qt) * 128 + q];
        M = fmaxf(M, m[f]);
    }
    float den = 0.f;
#pragma unroll
    for (int f = 0; f < SAI; f++) {
        wgt[f] = exp2f(m[f] - M);
        den += g_L[((size_t)(f * NB + b) * NQT + qt) * 128 + q] * wgt[f];
    }
    float dinv = 1.f / den;

#pragma unroll 4
    for (int ci = 0; ci < 16; ci++) {
        int c = cq * 16 + ci;
        float acc = 0.f;
#pragma unroll
        for (int f = 0; f < SAI; f++)
            acc += g_On[(size_t)((f * NB + b) * NQT + qt) * 8192 + c * 128 + q] * wgt[f];
        gO[((size_t)b * 64 + c) * HWN + qt * 128 + q] = acc * dinv;
    }
}

extern "C" void kernel_launch(void* const* d_in, const int* in_sizes, int n_in,
                              void* d_out, int out_size)
{
    const float* gK = (const float*)d_in[0];  // memory_keys   (9,4,64,32,32)
    const float* gV = (const float*)d_in[1];  // memory_values (9,4,64,32,32)
    const float* gQ = (const float*)d_in[2];  // query_query   (4,64,32,32)
    const float* gD = (const float*)d_in[3];  // disparity     (4,1,32,32)
    const int*   gS = (const int*)d_in[4];    // sequence_index(4,9,2)
    float* gO = (float*)d_out;                // (4,64,32,32)

    cudaFuncSetAttribute(cfa_main, cudaFuncAttributeMaxDynamicSharedMemorySize, SM_BYTES);

    prepass<<<SAI * NB * NGRP, 256>>>(gK, gV);
    dim3 gr(NQT, NB, SAI);
    cfa_main<<<gr, 256, SM_BYTES>>>(gQ, gD, gS);
    reduce_k<<<NB * NQT, 512>>>(gO);
}

// round 15
// speedup vs baseline: 4.3315x; 1.0279x over previous
#include <cuda_runtime.h>
#include <cuda_bf16.h>
#include <cstdint>
#include <math.h>

// CrossFrameAttention via mma.sync (tcgen05 feature-gated off under compute_103).
//   QK: bf16 hi/lo 3-term split; fragments via ldmatrix, manually double-buffered
//   softmax: per-warp online max in log2 domain (Q pre-scaled by log2e),
//            frames merged via log-sum-exp in reduce (split-k over frames)
//   AV: fp16 P x fp16 V single term
//   K/V tile loading: cp.async.bulk (2 ops/chunk) + mbarrier, replacing 1728
//   per-chunk cp.async ops.

#define SAI 9
#define NB 4
#define CKD 64
#define HWN 1024
#define NGRP 16
#define NQT 8

#define ROWB 144            // row pitch bytes (72 elems x 2B)
#define SPLITB 9216         // one split [64][72] bf16
#define KTILEB 18432        // K tile: [2 split][64][72]
#define VTILEB 9216         // V tile: [64ch][72key] fp16
#define QTILEB 18432        // one Q split: [128 q][72 ch] bf16
#define CHUNKB (KTILEB + VTILEB)

__device__ __align__(16) char g_KT[SAI * NB * NGRP * KTILEB];  // 10.6 MB
__device__ __align__(16) char g_VT[SAI * NB * NGRP * VTILEB];  // 5.3 MB
__device__ float g_On[SAI * NB * NQT * 64 * 128];              // 9.4 MB
__device__ float g_L [SAI * NB * NQT * 128];
__device__ float g_M [SAI * NB * NQT * 128];

// ---------------- helpers ----------------
__device__ __forceinline__ uint32_t smem_u32(const void* p) {
    uint32_t a;
    asm("{ .reg .u64 t; cvta.to.shared.u64 t, %1; cvt.u32.u64 %0, t; }" : "=r"(a) : "l"(p));
    return a;
}

__device__ __forceinline__ uint32_t cvt2bf(float hi, float lo) {
    uint32_t r;
    asm("cvt.rn.bf16x2.f32 %0, %1, %2;" : "=r"(r) : "f"(hi), "f"(lo));
    return r;
}

__device__ __forceinline__ uint32_t cvt2h(float hi, float lo) {
    uint32_t r;
    asm("cvt.rn.f16x2.f32 %0, %1, %2;" : "=r"(r) : "f"(hi), "f"(lo));
    return r;
}

__device__ __forceinline__ void ldsm4(uint32_t* r, uint32_t addr) {
    asm volatile("ldmatrix.sync.aligned.m8n8.x4.shared.b16 {%0,%1,%2,%3}, [%4];"
                 : "=r"(r[0]), "=r"(r[1]), "=r"(r[2]), "=r"(r[3]) : "r"(addr));
}

__device__ __forceinline__ void mma_bf16(float* c, const uint32_t* a,
                                         uint32_t b0, uint32_t b1) {
    asm volatile(
        "mma.sync.aligned.m16n8k16.row.col.f32.bf16.bf16.f32 "
        "{%0,%1,%2,%3}, {%4,%5,%6,%7}, {%8,%9}, {%0,%1,%2,%3};"
        : "+f"(c[0]), "+f"(c[1]), "+f"(c[2]), "+f"(c[3])
        : "r"(a[0]), "r"(a[1]), "r"(a[2]), "r"(a[3]), "r"(b0), "r"(b1));
}

__device__ __forceinline__ void mma_f16(float* c, const uint32_t* a,
                                        uint32_t b0, uint32_t b1) {
    asm volatile(
        "mma.sync.aligned.m16n8k16.row.col.f32.f16.f16.f32 "
        "{%0,%1,%2,%3}, {%4,%5,%6,%7}, {%8,%9}, {%0,%1,%2,%3};"
        : "+f"(c[0]), "+f"(c[1]), "+f"(c[2]), "+f"(c[3])
        : "r"(a[0]), "r"(a[1]), "r"(a[2]), "r"(a[3]), "r"(b0), "r"(b1));
}

// bulk async copy gmem -> smem with mbarrier complete_tx (sm_90 base feature)
__device__ __forceinline__ void bulk_ld(uint32_t dst, const void* src,
                                        uint32_t bytes, uint32_t mbar) {
    asm volatile(
        "cp.async.bulk.shared::cta.global.mbarrier::complete_tx::bytes "
        "[%0], [%1], %2, [%3];"
        :: "r"(dst), "l"(src), "r"(bytes), "r"(mbar) : "memory");
}

#define MBAR_INIT(m, c) \
    asm volatile("mbarrier.init.shared.b64 [%0], %1;" :: "r"(m), "r"(c) : "memory")
#define MBAR_EXPECT_TX(m, bytes) \
    asm volatile("mbarrier.arrive.expect_tx.shared.b64 _, [%0], %1;" \
                 :: "r"(m), "r"(bytes) : "memory")
#define FENCE_PROXY() asm volatile("fence.proxy.async.shared::cta;" ::: "memory")

__device__ __forceinline__ void mbar_wait(uint32_t mbar, uint32_t parity) {
    asm volatile(
        "{\n\t.reg .pred P1;\n\t"
        "WL_%=:\n\t"
        "mbarrier.try_wait.parity.acquire.cta.shared::cta.b64 P1, [%0], %1;\n\t"
        "@P1 bra.uni WD_%=;\n\t"
        "bra.uni WL_%=;\n\t"
        "WD_%=:\n\t}"
        :: "r"(mbar), "r"(parity) : "memory");
}

// ---------------- prepass ----------------
__global__ __launch_bounds__(256)
void prepass(const float* __restrict__ gK, const float* __restrict__ gV)
{
    __shared__ __nv_bfloat16 T[2][64][72];

    const int bx = blockIdx.x;
    const int grp = bx & 15, sb = bx >> 4;
    const int hwb = grp * 64;
    const int tid = threadIdx.x;

    const float* kb = gK + (size_t)sb * CKD * HWN + hwb;
    const float* vb = gV + (size_t)sb * CKD * HWN + hwb;

    // V direct: fp16 [ch][key]
    {
        char* dv = g_VT + (size_t)bx * VTILEB;
#pragma unroll
        for (int i = 0; i < 4; i++) {
            int idx = tid + i * 256;
            int c = idx >> 4, k4 = (idx & 15) * 4;
            float4 f = *(const float4*)(vb + (size_t)c * HWN + k4);
            uint2 h = make_uint2(cvt2h(f.y, f.x), cvt2h(f.w, f.z));
            *(uint2*)(dv + (size_t)c * ROWB + k4 * 2) = h;
        }
    }

    // K: transpose to [key][ch] h/l
#pragma unroll
    for (int i = 0; i < 16; i++) {
        int idx = tid + i * 256;
        int c = idx >> 6, k = idx & 63;
        float f = kb[(size_t)c * HWN + k];
        __nv_bfloat16 h = __float2bfloat16(f);
        T[0][k][c] = h;
        T[1][k][c] = __float2bfloat16(f - __bfloat162float(h));
    }
    __syncthreads();
    {
        const uint4* src = (const uint4*)&T[0][0][0];
        uint4* dst = (uint4*)(g_KT + (size_t)bx * KTILEB);
        for (int idx = tid; idx < 1152; idx += 256) dst[idx] = src[idx];
    }
}

// ---------------- main ----------------
// smem: [0,128) keep bitmask; [128,144) mbarriers full[2];
//       [256, +36864) Q [2 split][128][72] bf16;
//       [37120, +36864) K [2 slot][2 split][64][72];
//       [73984, +18432) V [2 slot][64][72] fp16
#define MBOFF 128
#define QOFF 256
#define KOFF 37120
#define VOFF 73984
#define SM_BYTES 92416

__global__ __launch_bounds__(256, 2)
void cfa_main(const float* __restrict__ gQ, const float* __restrict__ gD,
              const int* __restrict__ gS)
{
    extern __shared__ char raw[];
    uint32_t* KeepS = (uint32_t*)raw;
    const uint32_t sb32 = smem_u32(raw);
    const uint32_t QSB = sb32 + QOFF;
    const uint32_t KSB = sb32 + KOFF;
    const uint32_t VSB = sb32 + VOFF;

    const int qt = blockIdx.x, b = blockIdx.y, s = blockIdx.z;
    const int sb = s * NB + b;
    const int tid = threadIdx.x;
    const int w = tid >> 5, lane = tid & 31;
    const int g = lane >> 2, t = lane & 3;
    const int hw0 = qt * 128;

    // prologue: init mbarriers, kick off chunk 0 -> slot 0 (single thread)
    if (tid == 0) {
        MBAR_INIT(sb32 + MBOFF, 1);
        MBAR_INIT(sb32 + MBOFF + 8, 1);
        FENCE_PROXY();
        MBAR_EXPECT_TX(sb32 + MBOFF, CHUNKB);
        bulk_ld(KSB, g_KT + (size_t)(sb * NGRP) * KTILEB, KTILEB, sb32 + MBOFF);
        bulk_ld(VSB, g_VT + (size_t)(sb * NGRP) * VTILEB, VTILEB, sb32 + MBOFF);
    }

    // keep bitmask
    {
        float ddx = (float)gS[(b * SAI + s) * 2 + 0] - 5.f;
        float ddy = (float)gS[(b * SAI + s) * 2 + 1] - 5.f;
        float dist = sqrtf(ddx * ddx + ddy * ddy);
#pragma unroll
        for (int r = 0; r < 4; r++) {
            unsigned bit = fabsf(dist * gD[b * HWN + r * 256 + tid]) > 0.5f ? 1u : 0u;
            unsigned word = __ballot_sync(0xffffffffu, bit);
            if (lane == 0) KeepS[r * 8 + w] = word;
        }
    }

    // Q tile: [q][c] bf16 h/l into smem, PRE-SCALED by log2(e)
    {
        const float* qp = gQ + (size_t)b * CKD * HWN + hw0;
        __nv_bfloat16* qh = (__nv_bfloat16*)(raw + QOFF);
        __nv_bfloat16* ql = (__nv_bfloat16*)(raw + QOFF + QTILEB);
#pragma unroll
        for (int i = 0; i < 32; i++) {
            int idx = tid + i * 256;                 // 8192 = 64c x 128q
            int c = idx >> 7, q = idx & 127;
            float f = qp[(size_t)c * HWN + q] * 1.4426950408889634f;
            __nv_bfloat16 h = __float2bfloat16(f);
            qh[q * 72 + c] = h;
            ql[q * 72 + c] = __float2bfloat16(f - __bfloat162float(h));
        }
    }

    // ldsm addressing
    const uint32_t lrow = (uint32_t)((lane & 7) + ((lane >> 4) << 3)) * ROWB
                        + (uint32_t)(((lane >> 3) & 1) << 4);
    const uint32_t arow = (uint32_t)((lane & 7) + (((lane >> 3) & 1) << 3)) * ROWB
                        + (uint32_t)((lane >> 4) << 4);
    const uint32_t qbase = QSB + (uint32_t)(16 * w) * ROWB + arow;

    float Oacc[8][4];
#pragma unroll
    for (int j = 0; j < 8; j++)
#pragma unroll
        for (int r = 0; r < 4; r++) Oacc[j][r] = 0.f;
    float lrun0 = 0.f, lrun1 = 0.f;
    float m0 = -1e4f, m1 = -1e4f;        // log2-domain running max

    __syncthreads();   // mbars + Q tile + keep mask visible

    for (int gc = 0; gc < NGRP; gc++) {
        const int slot = gc & 1;
        const uint32_t mb = sb32 + MBOFF + slot * 8;

        mbar_wait(mb, (gc >> 1) & 1);    // chunk gc resident in slot
        __syncthreads();                 // all warps finished compute of gc-1

        // prefetch gc+1 into slot^1 (single thread, 2 bulk ops)
        if (tid == 0 && gc + 1 < NGRP) {
            const uint32_t mbn = sb32 + MBOFF + (slot ^ 1) * 8;
            MBAR_EXPECT_TX(mbn, CHUNKB);
            bulk_ld(KSB + (slot ^ 1) * KTILEB,
                    g_KT + (size_t)(sb * NGRP + gc + 1) * KTILEB, KTILEB, mbn);
            bulk_ld(VSB + (slot ^ 1) * VTILEB,
                    g_VT + (size_t)(sb * NGRP + gc + 1) * VTILEB, VTILEB, mbn);
        }

        const uint32_t kbase = KSB + slot * KTILEB;
        const uint32_t vbase = VSB + slot * VTILEB;

        // ---- S = Qh*Kh + Qh*Kl + Ql*Kh (K fragments double-buffered) ----
        float Sacc[8][4];
#pragma unroll
        for (int j = 0; j < 8; j++)
#pragma unroll
            for (int r = 0; r < 4; r++) Sacc[j][r] = 0.f;

#pragma unroll
        for (int kk = 0; kk < 4; kk++) {
            uint32_t qh[4], ql[4];
            ldsm4(qh, qbase + kk * 32);
            ldsm4(ql, qbase + kk * 32 + QTILEB);

            uint32_t kf[2][8];
            ldsm4(&kf[0][0], kbase + kk * 32 + lrow);
            ldsm4(&kf[0][4], kbase + kk * 32 + lrow + SPLITB);
#pragma unroll
            for (int np = 0; np < 4; np++) {
                const int nb = np & 1;
                if (np < 3) {
                    uint32_t ah = kbase + (np + 1) * (16 * ROWB) + kk * 32 + lrow;
                    ldsm4(&kf[nb ^ 1][0], ah);
                    ldsm4(&kf[nb ^ 1][4], ah + SPLITB);
                }
                const uint32_t* f = kf[nb];
                mma_bf16(Sacc[2 * np],     qh, f[0], f[1]);
                mma_bf16(Sacc[2 * np + 1], qh, f[2], f[3]);
                mma_bf16(Sacc[2 * np],     qh, f[4], f[5]);
                mma_bf16(Sacc[2 * np + 1], qh, f[6], f[7]);
                mma_bf16(Sacc[2 * np],     ql, f[0], f[1]);
                mma_bf16(Sacc[2 * np + 1], ql, f[2], f[3]);
            }
        }

        // ---- per-warp online max (UNMASKED — over-estimate is exact-ratio safe) ----
        float r0mx = -1e30f, r1mx = -1e30f;
#pragma unroll
        for (int j = 0; j < 8; j++) {
            r0mx = fmaxf(r0mx, fmaxf(Sacc[j][0], Sacc[j][1]));
            r1mx = fmaxf(r1mx, fmaxf(Sacc[j][2], Sacc[j][3]));
        }
        r0mx = fmaxf(r0mx, __shfl_xor_sync(0xffffffffu, r0mx, 1));
        r0mx = fmaxf(r0mx, __shfl_xor_sync(0xffffffffu, r0mx, 2));
        r1mx = fmaxf(r1mx, __shfl_xor_sync(0xffffffffu, r1mx, 1));
        r1mx = fmaxf(r1mx, __shfl_xor_sync(0xffffffffu, r1mx, 2));

        float m0n = fmaxf(m0, r0mx), m1n = fmaxf(m1, r1mx);
        float sc0 = exp2f(m0 - m0n), sc1 = exp2f(m1 - m1n);
        m0 = m0n; m1 = m1n;
#pragma unroll
        for (int j = 0; j < 8; j++) {
            Oacc[j][0] *= sc0; Oacc[j][1] *= sc0;
            Oacc[j][2] *= sc1; Oacc[j][3] *= sc1;
        }
        lrun0 *= sc0; lrun1 *= sc1;

        // ---- P = keep ? exp2(s - m) : 0 ; fp16 fragments ----
        const unsigned w0 = KeepS[2 * gc], w1 = KeepS[2 * gc + 1];
        uint32_t PhA[8], PhB[8];
#pragma unroll
        for (int j = 0; j < 8; j++) {
            unsigned sel = (j < 4) ? w0 : w1;
            int sh = ((8 * j) & 31) + 2 * t;
            bool kp0 = (sel >> sh) & 1;
            bool kp1 = (sel >> (sh + 1)) & 1;
            float p0 = kp0 ? exp2f(Sacc[j][0] - m0) : 0.f;
            float p1 = kp1 ? exp2f(Sacc[j][1] - m0) : 0.f;
            float p2 = kp0 ? exp2f(Sacc[j][2] - m1) : 0.f;
            float p3 = kp1 ? exp2f(Sacc[j][3] - m1) : 0.f;
            lrun0 += p0 + p1;
            lrun1 += p2 + p3;
            PhA[j] = cvt2h(p1, p0);
            PhB[j] = cvt2h(p3, p2);
        }

        // ---- O += P * V (V fragments double-buffered) ----
        {
            uint32_t vf[2][4];
            ldsm4(vf[0], vbase + lrow);
#pragma unroll
            for (int it = 0; it < 16; it++) {
                const int kk = it >> 2, np = it & 3;
                const int nb = it & 1;
                if (it < 15) {
                    const int kk2 = (it + 1) >> 2, np2 = (it + 1) & 3;
                    ldsm4(vf[nb ^ 1], vbase + np2 * (16 * ROWB) + kk2 * 32 + lrow);
                }
                uint32_t a[4] = {PhA[2 * kk], PhB[2 * kk], PhA[2 * kk + 1], PhB[2 * kk + 1]};
                mma_f16(Oacc[2 * np],     a, vf[nb][0], vf[nb][1]);
                mma_f16(Oacc[2 * np + 1], a, vf[nb][2], vf[nb][3]);
            }
        }
    }

    // ---- epilogue ----
    lrun0 += __shfl_xor_sync(0xffffffffu, lrun0, 1);
    lrun0 += __shfl_xor_sync(0xffffffffu, lrun0, 2);
    lrun1 += __shfl_xor_sync(0xffffffffu, lrun1, 1);
    lrun1 += __shfl_xor_sync(0xffffffffu, lrun1, 2);
    const size_t lb = (size_t)(sb * NQT + qt) * 128;
    if (t == 0) {
        g_L[lb + 16 * w + g]     = lrun0;
        g_L[lb + 16 * w + 8 + g] = lrun1;
        g_M[lb + 16 * w + g]     = m0;
        g_M[lb + 16 * w + 8 + g] = m1;
    }

    float* on = g_On + (size_t)(sb * NQT + qt) * 8192;   // [c][128 q]
    const int qa = 16 * w + g;
#pragma unroll
    for (int j = 0; j < 8; j++) {
        int c = 8 * j + 2 * t;
        on[(size_t)c * 128 + qa]           = Oacc[j][0];
        on[(size_t)(c + 1) * 128 + qa]     = Oacc[j][1];
        on[(size_t)c * 128 + qa + 8]       = Oacc[j][2];
        on[(size_t)(c + 1) * 128 + qa + 8] = Oacc[j][3];
    }
}

// ---------------- reduce: log-sum-exp merge over frames (log2 domain) ----------------
__global__ __launch_bounds__(512)
void reduce_k(float* __restrict__ gO)
{
    const int blk = blockIdx.x;              // b*8 + qt
    const int b = blk >> 3, qt = blk & 7;
    const int q = threadIdx.x & 127, cq = threadIdx.x >> 7;

    float m[SAI], wgt[SAI];
    float M = -1e30f;
#pragma unroll
    for (int f = 0; f < SAI; f++) {
        m[f] = g_M[((size_t)(f * NB + b) * NQT + qt) * 128 + q];
        M = fmaxf(M, m[f]);
    }
    float den = 0.f;
#pragma unroll
    for (int f = 0; f < SAI; f++) {
        wgt[f] = exp2f(m[f] - M);
        den += g_L[((size_t)(f * NB + b) * NQT + qt) * 128 + q] * wgt[f];
    }
    float dinv = 1.f / den;

#pragma unroll 4
    for (int ci = 0; ci < 16; ci++) {
        int c = cq * 16 + ci;
        float acc = 0.f;
#pragma unroll
        for (int f = 0; f < SAI; f++)
            acc += g_On[(size_t)((f * NB + b) * NQT + qt) * 8192 + c * 128 + q] * wgt[f];
        gO[((size_t)b * 64 + c) * HWN + qt * 128 + q] = acc * dinv;
    }
}

extern "C" void kernel_launch(void* const* d_in, const int* in_sizes, int n_in,
                              void* d_out, int out_size)
{
    const float* gK = (const float*)d_in[0];  // memory_keys   (9,4,64,32,32)
    const float* gV = (const float*)d_in[1];  // memory_values (9,4,64,32,32)
    const float* gQ = (const float*)d_in[2];  // query_query   (4,64,32,32)
    const float* gD = (const float*)d_in[3];  // disparity     (4,1,32,32)
    const int*   gS = (const int*)d_in[4];    // sequence_index(4,9,2)
    float* gO = (float*)d_out;                // (4,64,32,32)

    cudaFuncSetAttribute(cfa_main, cudaFuncAttributeMaxDynamicSharedMemorySize, SM_BYTES);

    prepass<<<SAI * NB * NGRP, 256>>>(gK, gV);
    dim3 gr(NQT, NB, SAI);
    cfa_main<<<gr, 256, SM_BYTES>>>(gQ, gD, gS);
    reduce_k<<<NB * NQT, 512>>>(gO);
}

// round 16
// speedup vs baseline: 5.5964x; 1.2920x over previous
#include <cuda_runtime.h>
#include <cuda_bf16.h>
#include <cstdint>
#include <math.h>

// CrossFrameAttention via mma.sync (tcgen05 feature-gated off under compute_103).
//   QK: bf16 hi/lo 3-term split; fragments via ldmatrix, manually double-buffered
//   softmax: per-warp online max in log2 domain (Q pre-scaled by log2e);
//            P = ex2.approx.f16x2 (packed); l accumulated by ones-MMA;
//            frames merged via log-sum-exp in reduce (split-k over frames)
//   AV: fp16 P x fp16 V single term
//   K/V tiles: cp.async.bulk + mbarrier double buffering

#define SAI 9
#define NB 4
#define CKD 64
#define HWN 1024
#define NGRP 16
#define NQT 8

#define ROWB 144            // row pitch bytes (72 elems x 2B)
#define SPLITB 9216         // one split [64][72] bf16
#define KTILEB 18432        // K tile: [2 split][64][72]
#define VTILEB 9216         // V tile: [64ch][72key] fp16
#define QTILEB 18432        // one Q split: [128 q][72 ch] bf16
#define CHUNKB (KTILEB + VTILEB)

__device__ __align__(16) char g_KT[SAI * NB * NGRP * KTILEB];  // 10.6 MB
__device__ __align__(16) char g_VT[SAI * NB * NGRP * VTILEB];  // 5.3 MB
__device__ float g_On[SAI * NB * NQT * 64 * 128];              // 9.4 MB
__device__ float g_L [SAI * NB * NQT * 128];
__device__ float g_M [SAI * NB * NQT * 128];

// ---------------- helpers ----------------
__device__ __forceinline__ uint32_t smem_u32(const void* p) {
    uint32_t a;
    asm("{ .reg .u64 t; cvta.to.shared.u64 t, %1; cvt.u32.u64 %0, t; }" : "=r"(a) : "l"(p));
    return a;
}

__device__ __forceinline__ uint32_t cvt2bf(float hi, float lo) {
    uint32_t r;
    asm("cvt.rn.bf16x2.f32 %0, %1, %2;" : "=r"(r) : "f"(hi), "f"(lo));
    return r;
}

__device__ __forceinline__ uint32_t cvt2h(float hi, float lo) {
    uint32_t r;
    asm("cvt.rn.f16x2.f32 %0, %1, %2;" : "=r"(r) : "f"(hi), "f"(lo));
    return r;
}

__device__ __forceinline__ uint32_t hex2(uint32_t x) {
    uint32_t r;
    asm("ex2.approx.f16x2 %0, %1;" : "=r"(r) : "r"(x));
    return r;
}

__device__ __forceinline__ void ldsm4(uint32_t* r, uint32_t addr) {
    asm volatile("ldmatrix.sync.aligned.m8n8.x4.shared.b16 {%0,%1,%2,%3}, [%4];"
                 : "=r"(r[0]), "=r"(r[1]), "=r"(r[2]), "=r"(r[3]) : "r"(addr));
}

__device__ __forceinline__ void mma_bf16(float* c, const uint32_t* a,
                                         uint32_t b0, uint32_t b1) {
    asm volatile(
        "mma.sync.aligned.m16n8k16.row.col.f32.bf16.bf16.f32 "
        "{%0,%1,%2,%3}, {%4,%5,%6,%7}, {%8,%9}, {%0,%1,%2,%3};"
        : "+f"(c[0]), "+f"(c[1]), "+f"(c[2]), "+f"(c[3])
        : "r"(a[0]), "r"(a[1]), "r"(a[2]), "r"(a[3]), "r"(b0), "r"(b1));
}

__device__ __forceinline__ void mma_f16(float* c, const uint32_t* a,
                                        uint32_t b0, uint32_t b1) {
    asm volatile(
        "mma.sync.aligned.m16n8k16.row.col.f32.f16.f16.f32 "
        "{%0,%1,%2,%3}, {%4,%5,%6,%7}, {%8,%9}, {%0,%1,%2,%3};"
        : "+f"(c[0]), "+f"(c[1]), "+f"(c[2]), "+f"(c[3])
        : "r"(a[0]), "r"(a[1]), "r"(a[2]), "r"(a[3]), "r"(b0), "r"(b1));
}

// bulk async copy gmem -> smem with mbarrier complete_tx
__device__ __forceinline__ void bulk_ld(uint32_t dst, const void* src,
                                        uint32_t bytes, uint32_t mbar) {
    asm volatile(
        "cp.async.bulk.shared::cta.global.mbarrier::complete_tx::bytes "
        "[%0], [%1], %2, [%3];"
        :: "r"(dst), "l"(src), "r"(bytes), "r"(mbar) : "memory");
}

#define MBAR_INIT(m, c) \
    asm volatile("mbarrier.init.shared.b64 [%0], %1;" :: "r"(m), "r"(c) : "memory")
#define MBAR_EXPECT_TX(m, bytes) \
    asm volatile("mbarrier.arrive.expect_tx.shared.b64 _, [%0], %1;" \
                 :: "r"(m), "r"(bytes) : "memory")
#define FENCE_PROXY() asm volatile("fence.proxy.async.shared::cta;" ::: "memory")

__device__ __forceinline__ void mbar_wait(uint32_t mbar, uint32_t parity) {
    asm volatile(
        "{\n\t.reg .pred P1;\n\t"
        "WL_%=:\n\t"
        "mbarrier.try_wait.parity.acquire.cta.shared::cta.b64 P1, [%0], %1;\n\t"
        "@P1 bra.uni WD_%=;\n\t"
        "bra.uni WL_%=;\n\t"
        "WD_%=:\n\t}"
        :: "r"(mbar), "r"(parity) : "memory");
}

// ---------------- prepass ----------------
__global__ __launch_bounds__(256)
void prepass(const float* __restrict__ gK, const float* __restrict__ gV)
{
    __shared__ __nv_bfloat16 T[2][64][72];

    const int bx = blockIdx.x;
    const int grp = bx & 15, sb = bx >> 4;
    const int hwb = grp * 64;
    const int tid = threadIdx.x;

    const float* kb = gK + (size_t)sb * CKD * HWN + hwb;
    const float* vb = gV + (size_t)sb * CKD * HWN + hwb;

    // V direct: fp16 [ch][key]
    {
        char* dv = g_VT + (size_t)bx * VTILEB;
#pragma unroll
        for (int i = 0; i < 4; i++) {
            int idx = tid + i * 256;
            int c = idx >> 4, k4 = (idx & 15) * 4;
            float4 f = *(const float4*)(vb + (size_t)c * HWN + k4);
            uint2 h = make_uint2(cvt2h(f.y, f.x), cvt2h(f.w, f.z));
            *(uint2*)(dv + (size_t)c * ROWB + k4 * 2) = h;
        }
    }

    // K: transpose to [key][ch] h/l
#pragma unroll
    for (int i = 0; i < 16; i++) {
        int idx = tid + i * 256;
        int c = idx >> 6, k = idx & 63;
        float f = kb[(size_t)c * HWN + k];
        __nv_bfloat16 h = __float2bfloat16(f);
        T[0][k][c] = h;
        T[1][k][c] = __float2bfloat16(f - __bfloat162float(h));
    }
    __syncthreads();
    {
        const uint4* src = (const uint4*)&T[0][0][0];
        uint4* dst = (uint4*)(g_KT + (size_t)bx * KTILEB);
        for (int idx = tid; idx < 1152; idx += 256) dst[idx] = src[idx];
    }
}

// ---------------- main ----------------
// smem: [0,128) keep bitmask; [128,144) mbarriers full[2];
//       [256, +36864) Q [2 split][128][72] bf16;
//       [37120, +36864) K [2 slot][2 split][64][72];
//       [73984, +18432) V [2 slot][64][72] fp16
#define MBOFF 128
#define QOFF 256
#define KOFF 37120
#define VOFF 73984
#define SM_BYTES 92416

__global__ __launch_bounds__(256, 2)
void cfa_main(const float* __restrict__ gQ, const float* __restrict__ gD,
              const int* __restrict__ gS)
{
    extern __shared__ char raw[];
    uint32_t* KeepS = (uint32_t*)raw;
    const uint32_t sb32 = smem_u32(raw);
    const uint32_t QSB = sb32 + QOFF;
    const uint32_t KSB = sb32 + KOFF;
    const uint32_t VSB = sb32 + VOFF;

    const int qt = blockIdx.x, b = blockIdx.y, s = blockIdx.z;
    const int sb = s * NB + b;
    const int tid = threadIdx.x;
    const int w = tid >> 5, lane = tid & 31;
    const int g = lane >> 2, t = lane & 3;
    const int hw0 = qt * 128;

    // prologue: init mbarriers, kick off chunk 0 -> slot 0 (single thread)
    if (tid == 0) {
        MBAR_INIT(sb32 + MBOFF, 1);
        MBAR_INIT(sb32 + MBOFF + 8, 1);
        FENCE_PROXY();
        MBAR_EXPECT_TX(sb32 + MBOFF, CHUNKB);
        bulk_ld(KSB, g_KT + (size_t)(sb * NGRP) * KTILEB, KTILEB, sb32 + MBOFF);
        bulk_ld(VSB, g_VT + (size_t)(sb * NGRP) * VTILEB, VTILEB, sb32 + MBOFF);
    }

    // keep bitmask
    {
        float ddx = (float)gS[(b * SAI + s) * 2 + 0] - 5.f;
        float ddy = (float)gS[(b * SAI + s) * 2 + 1] - 5.f;
        float dist = sqrtf(ddx * ddx + ddy * ddy);
#pragma unroll
        for (int r = 0; r < 4; r++) {
            unsigned bit = fabsf(dist * gD[b * HWN + r * 256 + tid]) > 0.5f ? 1u : 0u;
            unsigned word = __ballot_sync(0xffffffffu, bit);
            if (lane == 0) KeepS[r * 8 + w] = word;
        }
    }

    // Q tile: [q][c] bf16 h/l into smem, PRE-SCALED by log2(e)
    {
        const float* qp = gQ + (size_t)b * CKD * HWN + hw0;
        __nv_bfloat16* qh = (__nv_bfloat16*)(raw + QOFF);
        __nv_bfloat16* ql = (__nv_bfloat16*)(raw + QOFF + QTILEB);
#pragma unroll
        for (int i = 0; i < 32; i++) {
            int idx = tid + i * 256;                 // 8192 = 64c x 128q
            int c = idx >> 7, q = idx & 127;
            float f = qp[(size_t)c * HWN + q] * 1.4426950408889634f;
            __nv_bfloat16 h = __float2bfloat16(f);
            qh[q * 72 + c] = h;
            ql[q * 72 + c] = __float2bfloat16(f - __bfloat162float(h));
        }
    }

    // ldsm addressing
    const uint32_t lrow = (uint32_t)((lane & 7) + ((lane >> 4) << 3)) * ROWB
                        + (uint32_t)(((lane >> 3) & 1) << 4);
    const uint32_t arow = (uint32_t)((lane & 7) + (((lane >> 3) & 1) << 3)) * ROWB
                        + (uint32_t)((lane >> 4) << 4);
    const uint32_t qbase = QSB + (uint32_t)(16 * w) * ROWB + arow;

    float Oacc[8][4];
#pragma unroll
    for (int j = 0; j < 8; j++)
#pragma unroll
        for (int r = 0; r < 4; r++) Oacc[j][r] = 0.f;
    float Lacc[4] = {0.f, 0.f, 0.f, 0.f};   // ones-MMA accumulator: [0]=l(qa), [2]=l(qa+8)
    float m0 = -1e4f, m1 = -1e4f;            // log2-domain running max
    const uint32_t ONES2 = 0x3C003C00u;      // fp16x2 {1.0, 1.0}

    __syncthreads();   // mbars + Q tile + keep mask visible

    for (int gc = 0; gc < NGRP; gc++) {
        const int slot = gc & 1;
        const uint32_t mb = sb32 + MBOFF + slot * 8;

        mbar_wait(mb, (gc >> 1) & 1);    // chunk gc resident in slot
        __syncthreads();                 // all warps finished compute of gc-1

        // prefetch gc+1 into slot^1 (single thread, 2 bulk ops)
        if (tid == 0 && gc + 1 < NGRP) {
            const uint32_t mbn = sb32 + MBOFF + (slot ^ 1) * 8;
            MBAR_EXPECT_TX(mbn, CHUNKB);
            bulk_ld(KSB + (slot ^ 1) * KTILEB,
                    g_KT + (size_t)(sb * NGRP + gc + 1) * KTILEB, KTILEB, mbn);
            bulk_ld(VSB + (slot ^ 1) * VTILEB,
                    g_VT + (size_t)(sb * NGRP + gc + 1) * VTILEB, VTILEB, mbn);
        }

        const uint32_t kbase = KSB + slot * KTILEB;
        const uint32_t vbase = VSB + slot * VTILEB;

        // ---- S = Qh*Kh + Qh*Kl + Ql*Kh (K fragments double-buffered) ----
        float Sacc[8][4];
#pragma unroll
        for (int j = 0; j < 8; j++)
#pragma unroll
            for (int r = 0; r < 4; r++) Sacc[j][r] = 0.f;

#pragma unroll
        for (int kk = 0; kk < 4; kk++) {
            uint32_t qh[4], ql[4];
            ldsm4(qh, qbase + kk * 32);
            ldsm4(ql, qbase + kk * 32 + QTILEB);

            uint32_t kf[2][8];
            ldsm4(&kf[0][0], kbase + kk * 32 + lrow);
            ldsm4(&kf[0][4], kbase + kk * 32 + lrow + SPLITB);
#pragma unroll
            for (int np = 0; np < 4; np++) {
                const int nb = np & 1;
                if (np < 3) {
                    uint32_t ah = kbase + (np + 1) * (16 * ROWB) + kk * 32 + lrow;
                    ldsm4(&kf[nb ^ 1][0], ah);
                    ldsm4(&kf[nb ^ 1][4], ah + SPLITB);
                }
                const uint32_t* f = kf[nb];
                mma_bf16(Sacc[2 * np],     qh, f[0], f[1]);
                mma_bf16(Sacc[2 * np + 1], qh, f[2], f[3]);
                mma_bf16(Sacc[2 * np],     qh, f[4], f[5]);
                mma_bf16(Sacc[2 * np + 1], qh, f[6], f[7]);
                mma_bf16(Sacc[2 * np],     ql, f[0], f[1]);
                mma_bf16(Sacc[2 * np + 1], ql, f[2], f[3]);
            }
        }

        // ---- per-warp online max (unmasked; over-estimate is ratio-safe) ----
        float r0mx = -1e30f, r1mx = -1e30f;
#pragma unroll
        for (int j = 0; j < 8; j++) {
            r0mx = fmaxf(r0mx, fmaxf(Sacc[j][0], Sacc[j][1]));
            r1mx = fmaxf(r1mx, fmaxf(Sacc[j][2], Sacc[j][3]));
        }
        r0mx = fmaxf(r0mx, __shfl_xor_sync(0xffffffffu, r0mx, 1));
        r0mx = fmaxf(r0mx, __shfl_xor_sync(0xffffffffu, r0mx, 2));
        r1mx = fmaxf(r1mx, __shfl_xor_sync(0xffffffffu, r1mx, 1));
        r1mx = fmaxf(r1mx, __shfl_xor_sync(0xffffffffu, r1mx, 2));

        float m0n = fmaxf(m0, r0mx), m1n = fmaxf(m1, r1mx);
        float sc0 = exp2f(m0 - m0n), sc1 = exp2f(m1 - m1n);
        m0 = m0n; m1 = m1n;
#pragma unroll
        for (int j = 0; j < 8; j++) {
            Oacc[j][0] *= sc0; Oacc[j][1] *= sc0;
            Oacc[j][2] *= sc1; Oacc[j][3] *= sc1;
        }
        Lacc[0] *= sc0; Lacc[2] *= sc1;

        // ---- P = mask & ex2.f16x2(s - m) ; fp16 fragments ----
        const unsigned w0 = KeepS[2 * gc], w1 = KeepS[2 * gc + 1];
        uint32_t PhA[8], PhB[8];
#pragma unroll
        for (int j = 0; j < 8; j++) {
            unsigned sel = (j < 4) ? w0 : w1;
            int sh = ((8 * j) & 31) + 2 * t;
            uint32_t mw = (((sel >> sh) & 1) ? 0x0000FFFFu : 0u)
                        | (((sel >> (sh + 1)) & 1) ? 0xFFFF0000u : 0u);
            uint32_t eA = cvt2h(Sacc[j][1] - m0, Sacc[j][0] - m0);
            uint32_t eB = cvt2h(Sacc[j][3] - m1, Sacc[j][2] - m1);
            PhA[j] = hex2(eA) & mw;
            PhB[j] = hex2(eB) & mw;
        }

        // ---- l += P * ones (4 MMAs; all B columns identical -> c0/c2 = row sums) ----
#pragma unroll
        for (int kk = 0; kk < 4; kk++) {
            uint32_t a[4] = {PhA[2 * kk], PhB[2 * kk], PhA[2 * kk + 1], PhB[2 * kk + 1]};
            mma_f16(Lacc, a, ONES2, ONES2);
        }

        // ---- O += P * V (V fragments double-buffered) ----
        {
            uint32_t vf[2][4];
            ldsm4(vf[0], vbase + lrow);
#pragma unroll
            for (int it = 0; it < 16; it++) {
                const int kk = it >> 2, np = it & 3;
                const int nb = it & 1;
                if (it < 15) {
                    const int kk2 = (it + 1) >> 2, np2 = (it + 1) & 3;
                    ldsm4(vf[nb ^ 1], vbase + np2 * (16 * ROWB) + kk2 * 32 + lrow);
                }
                uint32_t a[4] = {PhA[2 * kk], PhB[2 * kk], PhA[2 * kk + 1], PhB[2 * kk + 1]};
                mma_f16(Oacc[2 * np],     a, vf[nb][0], vf[nb][1]);
                mma_f16(Oacc[2 * np + 1], a, vf[nb][2], vf[nb][3]);
            }
        }
    }

    // ---- epilogue (Lacc[0]/Lacc[2] are complete row sums; no shfl needed) ----
    const size_t lb = (size_t)(sb * NQT + qt) * 128;
    if (t == 0) {
        g_L[lb + 16 * w + g]     = Lacc[0];
        g_L[lb + 16 * w + 8 + g] = Lacc[2];
        g_M[lb + 16 * w + g]     = m0;
        g_M[lb + 16 * w + 8 + g] = m1;
    }

    float* on = g_On + (size_t)(sb * NQT + qt) * 8192;   // [c][128 q]
    const int qa = 16 * w + g;
#pragma unroll
    for (int j = 0; j < 8; j++) {
        int c = 8 * j + 2 * t;
        on[(size_t)c * 128 + qa]           = Oacc[j][0];
        on[(size_t)(c + 1) * 128 + qa]     = Oacc[j][1];
        on[(size_t)c * 128 + qa + 8]       = Oacc[j][2];
        on[(size_t)(c + 1) * 128 + qa + 8] = Oacc[j][3];
    }
}

// ---------------- reduce: log-sum-exp merge over frames (log2 domain) ----------------
// grid = NB*NQT*4 (c split 4-way), 512 threads, 4 c's per thread
__global__ __launch_bounds__(512)
void reduce_k(float* __restrict__ gO)
{
    const int blk = blockIdx.x;              // ((b*8 + qt)*4 + cpart)
    const int cpart = blk & 3;
    const int qt = (blk >> 2) & 7;
    const int b = blk >> 5;
    const int q = threadIdx.x & 127, cq = threadIdx.x >> 7;

    float m[SAI], wgt[SAI];
    float M = -1e30f;
#pragma unroll
    for (int f = 0; f < SAI; f++) {
        m[f] = g_M[((size_t)(f * NB + b) * NQT + qt) * 128 + q];
        M = fmaxf(M, m[f]);
    }
    float den = 0.f;
#pragma unroll
    for (int f = 0; f < SAI; f++) {
        wgt[f] = exp2f(m[f] - M);
        den += g_L[((size_t)(f * NB + b) * NQT + qt) * 128 + q] * wgt[f];
    }
    float dinv = 1.f / den;

#pragma unroll
    for (int ci = 0; ci < 4; ci++) {
        int c = cpart * 16 + cq * 4 + ci;
        float acc = 0.f;
#pragma unroll
        for (int f = 0; f < SAI; f++)
            acc += g_On[(size_t)((f * NB + b) * NQT + qt) * 8192 + c * 128 + q] * wgt[f];
        gO[((size_t)b * 64 + c) * HWN + qt * 128 + q] = acc * dinv;
    }
}

extern "C" void kernel_launch(void* const* d_in, const int* in_sizes, int n_in,
                              void* d_out, int out_size)
{
    const float* gK = (const float*)d_in[0];  // memory_keys   (9,4,64,32,32)
    const float* gV = (const float*)d_in[1];  // memory_values (9,4,64,32,32)
    const float* gQ = (const float*)d_in[2];  // query_query   (4,64,32,32)
    const float* gD = (const float*)d_in[3];  // disparity     (4,1,32,32)
    const int*   gS = (const int*)d_in[4];    // sequence_index(4,9,2)
    float* gO = (float*)d_out;                // (4,64,32,32)

    cudaFuncSetAttribute(cfa_main, cudaFuncAttributeMaxDynamicSharedMemorySize, SM_BYTES);

    prepass<<<SAI * NB * NGRP, 256>>>(gK, gV);
    dim3 gr(NQT, NB, SAI);
    cfa_main<<<gr, 256, SM_BYTES>>>(gQ, gD, gS);
    reduce_k<<<NB * NQT * 4, 512>>>(gO);
}